// round 1
// baseline (speedup 1.0000x reference)
#include <cuda_runtime.h>
#include <math.h>

// Problem constants
#define NTOK   294912          // N*H*W = 32*96*96
#define BM     64              // tokens per block
#define NBLK   (NTOK / BM)     // 4608
#define THREADS 256
#define SX     260             // row stride (floats) for 64x256 tiles (pad 4)
#define SW     260             // row stride for W k-slice tile

// smem layout (floats):
//   x_s  : 64*260 = 16640
//   a_s  : 16640
//   b_s  : 16640
//   w_s  : 16*260 = 4160
//   stat : 64*20  = 1280
//   cls  : 64
#define SMEM_FLOATS (16640*3 + 4160 + 1280 + 64)
#define SMEM_BYTES  (SMEM_FLOATS * 4)

__device__ __forceinline__ float sigmoidf_(float v) {
    return 1.0f / (1.0f + __expf(-v));
}

// out_s[t][j] = act( sum_k in_s[t][k] * Wg[j][k] + bias[j] ), 64x256 tile, K=256
__device__ __forceinline__ void gemm_tile(
    const float* __restrict__ in_s,    // [64][SX]
    const float* __restrict__ Wg,      // [256][256] row-major (out x in)
    const float* __restrict__ bias,    // [256]
    float*       __restrict__ out_s,   // [64][SX]
    float*       __restrict__ w_s,     // [16][SW]
    int tid, bool do_relu)
{
    const int warp = tid >> 5;
    const int lane = tid & 31;
    const int r0 = warp << 3;          // 8 token rows per warp
    const int c0 = lane << 3;          // 8 output cols per lane

    float acc[8][8];
#pragma unroll
    for (int i = 0; i < 8; i++)
#pragma unroll
        for (int j = 0; j < 8; j++) acc[i][j] = 0.0f;

    const int jj = tid >> 2;           // 0..63 : output row group for W load
    const int f4 = (tid & 3) << 2;     // which 4-k chunk

    for (int kc = 0; kc < 256; kc += 16) {
        __syncthreads();               // previous slice fully consumed
        // load W[j][kc..kc+16] k-slice, transposed to w_s[kk][j]
#pragma unroll
        for (int rr = 0; rr < 4; rr++) {
            int j = jj + (rr << 6);
            float4 v = *(const float4*)(Wg + j * 256 + kc + f4);
            w_s[(f4 + 0) * SW + j] = v.x;
            w_s[(f4 + 1) * SW + j] = v.y;
            w_s[(f4 + 2) * SW + j] = v.z;
            w_s[(f4 + 3) * SW + j] = v.w;
        }
        __syncthreads();

#pragma unroll
        for (int k = 0; k < 16; k++) {
            float b[8];
            float4 b0 = *(const float4*)(w_s + k * SW + c0);
            float4 b1 = *(const float4*)(w_s + k * SW + c0 + 4);
            b[0] = b0.x; b[1] = b0.y; b[2] = b0.z; b[3] = b0.w;
            b[4] = b1.x; b[5] = b1.y; b[6] = b1.z; b[7] = b1.w;
#pragma unroll
            for (int i = 0; i < 8; i++) {
                float a = in_s[(r0 + i) * SX + kc + k];   // warp-broadcast LDS
#pragma unroll
                for (int j = 0; j < 8; j++) acc[i][j] = fmaf(a, b[j], acc[i][j]);
            }
        }
    }

    float bv[8];
#pragma unroll
    for (int j = 0; j < 8; j++) bv[j] = bias[c0 + j];

#pragma unroll
    for (int i = 0; i < 8; i++) {
        float4 o0, o1;
        o0.x = acc[i][0] + bv[0]; o0.y = acc[i][1] + bv[1];
        o0.z = acc[i][2] + bv[2]; o0.w = acc[i][3] + bv[3];
        o1.x = acc[i][4] + bv[4]; o1.y = acc[i][5] + bv[5];
        o1.z = acc[i][6] + bv[6]; o1.w = acc[i][7] + bv[7];
        if (do_relu) {
            o0.x = fmaxf(o0.x, 0.f); o0.y = fmaxf(o0.y, 0.f);
            o0.z = fmaxf(o0.z, 0.f); o0.w = fmaxf(o0.w, 0.f);
            o1.x = fmaxf(o1.x, 0.f); o1.y = fmaxf(o1.y, 0.f);
            o1.z = fmaxf(o1.z, 0.f); o1.w = fmaxf(o1.w, 0.f);
        }
        *(float4*)(out_s + (r0 + i) * SX + c0)     = o0;
        *(float4*)(out_s + (r0 + i) * SX + c0 + 4) = o1;
    }
    __syncthreads();                   // results visible to whole block
}

__global__ void __launch_bounds__(THREADS, 1) gfocal_kernel(
    const float* __restrict__ x,
    const float* __restrict__ cw1, const float* __restrict__ cb1,
    const float* __restrict__ cw2, const float* __restrict__ cb2,
    const float* __restrict__ cw3, const float* __restrict__ cb3,
    const float* __restrict__ rw1, const float* __restrict__ rb1,
    const float* __restrict__ rw2, const float* __restrict__ rb2,
    const float* __restrict__ rw3, const float* __restrict__ rb3,
    const float* __restrict__ qw1, const float* __restrict__ qb1,
    const float* __restrict__ qw2, const float* __restrict__ qb2,
    float* __restrict__ cls_out,   // NTOK
    float* __restrict__ box_out,   // NTOK*4
    float* __restrict__ reg_out)   // NTOK*68
{
    extern __shared__ float smem[];
    float* x_s    = smem;
    float* a_s    = x_s + BM * SX;
    float* b_s    = a_s + BM * SX;
    float* w_s    = b_s + BM * SX;
    float* stat_s = w_s + 16 * SW;
    float* cls_s  = stat_s + BM * 20;

    const int tid = threadIdx.x;
    const int base = blockIdx.x * BM;

    // ---- load x tile (64 x 256) coalesced ----
    for (int idx = tid; idx < BM * 64; idx += THREADS) {
        int row = idx >> 6;
        int c4  = (idx & 63) << 2;
        *(float4*)(x_s + row * SX + c4) =
            *(const float4*)(x + (base + row) * 256 + c4);
    }
    // (gemm's first __syncthreads covers the x_s hazard)

    // ---- regression branch: layers 1,2 ----
    gemm_tile(x_s, rw1, rb1, a_s, w_s, tid, true);
    gemm_tile(a_s, rw2, rb2, b_s, w_s, tid, true);

    // ---- regression layer 3 (68 outs) + softmax/top4/integral epilogue ----
    {
        const int token = tid & 63;
        const int g     = tid >> 6;          // uniform per warp -> W loads broadcast
        const float* h  = b_s + token * SX;
        const float* wr = rw3 + (g * 17) * 256;

        float acc[17];
#pragma unroll
        for (int j = 0; j < 17; j++) acc[j] = rb3[g * 17 + j];

        for (int kc = 0; kc < 256; kc += 4) {
            float4 hv = *(const float4*)(h + kc);
#pragma unroll
            for (int j = 0; j < 17; j++) {
                float4 wv = *(const float4*)(wr + j * 256 + kc);
                acc[j] = fmaf(hv.x, wv.x, acc[j]);
                acc[j] = fmaf(hv.y, wv.y, acc[j]);
                acc[j] = fmaf(hv.z, wv.z, acc[j]);
                acc[j] = fmaf(hv.w, wv.w, acc[j]);
            }
        }

        // stage raw logits into a_s (free) for coalesced global write
#pragma unroll
        for (int j = 0; j < 17; j++) a_s[token * SX + g * 17 + j] = acc[j];

        // softmax over 17 bins
        float m = acc[0];
#pragma unroll
        for (int j = 1; j < 17; j++) m = fmaxf(m, acc[j]);
        float e[17];
        float s = 0.f, si = 0.f;
#pragma unroll
        for (int j = 0; j < 17; j++) {
            e[j] = __expf(acc[j] - m);
            s  += e[j];
            si += e[j] * (float)j;
        }
        // integral box
        box_out[(base + token) * 4 + g] = si / (s * 16.0f);

        // top-4 (descending, first-index ties) + mean
        float inv = 1.0f / s;
        float tsum = 0.f;
        float top[4];
#pragma unroll
        for (int t4 = 0; t4 < 4; t4++) {
            float mv = -1.0f; int mi = 0;
#pragma unroll
            for (int j = 0; j < 17; j++) {
                if (e[j] > mv) { mv = e[j]; mi = j; }
            }
            top[t4] = mv * inv;
            tsum += top[t4];
            e[mi] = -1.0f;
        }
#pragma unroll
        for (int t4 = 0; t4 < 4; t4++)
            stat_s[token * 20 + g * 5 + t4] = top[t4];
        stat_s[token * 20 + g * 5 + 4] = tsum * 0.25f;
    }
    __syncthreads();

    // coalesced reg_pred store (64 x 68)
    for (int idx = tid; idx < BM * 68; idx += THREADS) {
        int row = idx / 68;
        int col = idx - row * 68;
        reg_out[(base + row) * 68 + col] = a_s[row * SX + col];
    }

    // ---- classification branch: layers 1,2 ----
    gemm_tile(x_s, cw1, cb1, a_s, w_s, tid, true);
    gemm_tile(a_s, cw2, cb2, b_s, w_s, tid, true);

    // cls layer 3 (1 out per token): threads 0..63
    if (tid < 64) {
        const float* h = b_s + tid * SX;
        float sacc = cb3[0];
        for (int kc = 0; kc < 256; kc += 4) {
            float4 hv = *(const float4*)(h + kc);
            float4 wv = *(const float4*)(cw3 + kc);
            sacc = fmaf(hv.x, wv.x, sacc);
            sacc = fmaf(hv.y, wv.y, sacc);
            sacc = fmaf(hv.z, wv.z, sacc);
            sacc = fmaf(hv.w, wv.w, sacc);
        }
        cls_s[tid] = sacc;
    }
    __syncthreads();

    // quality head: load qw1 (64x20) into w_s (free)
    for (int idx = tid; idx < 64 * 20; idx += THREADS) w_s[idx] = qw1[idx];
    __syncthreads();

    if (tid < 64) {
        const float* st = stat_s + tid * 20;
        float q = qb2[0];
        for (int o = 0; o < 64; o++) {
            float hsum = qb1[o];
#pragma unroll
            for (int c = 0; c < 20; c++)
                hsum = fmaf(w_s[o * 20 + c], st[c], hsum);
            hsum = fmaxf(hsum, 0.0f);
            q = fmaf(hsum, qw2[o], q);
        }
        float quality = sigmoidf_(q);
        float cls     = sigmoidf_(cls_s[tid]);
        cls_out[base + tid] = cls * quality;
    }
}

extern "C" void kernel_launch(void* const* d_in, const int* in_sizes, int n_in,
                              void* d_out, int out_size)
{
    const float* x   = (const float*)d_in[0];
    const float* cw1 = (const float*)d_in[1];
    const float* cb1 = (const float*)d_in[2];
    const float* cw2 = (const float*)d_in[3];
    const float* cb2 = (const float*)d_in[4];
    const float* cw3 = (const float*)d_in[5];
    const float* cb3 = (const float*)d_in[6];
    const float* rw1 = (const float*)d_in[7];
    const float* rb1 = (const float*)d_in[8];
    const float* rw2 = (const float*)d_in[9];
    const float* rb2 = (const float*)d_in[10];
    const float* rw3 = (const float*)d_in[11];
    const float* rb3 = (const float*)d_in[12];
    const float* qw1 = (const float*)d_in[13];
    const float* qb1 = (const float*)d_in[14];
    const float* qw2 = (const float*)d_in[15];
    const float* qb2 = (const float*)d_in[16];

    float* out = (float*)d_out;
    // outputs concatenated in reference return order:
    // cls_score (N*1*H*W) | box (N*H*W*4) | reg_pred (N*H*W*68)
    float* cls_out = out;
    float* box_out = out + NTOK;
    float* reg_out = out + NTOK + NTOK * 4;

    cudaFuncSetAttribute(gfocal_kernel,
                         cudaFuncAttributeMaxDynamicSharedMemorySize, SMEM_BYTES);

    gfocal_kernel<<<NBLK, THREADS, SMEM_BYTES>>>(
        x, cw1, cb1, cw2, cb2, cw3, cb3,
        rw1, rb1, rw2, rb2, rw3, rb3,
        qw1, qb1, qw2, qb2,
        cls_out, box_out, reg_out);
}

// round 3
// speedup vs baseline: 2.2638x; 2.2638x over previous
#include <cuda_runtime.h>
#include <cuda_bf16.h>
#include <stdint.h>

#define NTOK    294912
#define BM      128
#define NBLK    (NTOK / BM)      // 2304
#define THREADS 512

// ---- smem byte offsets ----
#define OFF_A_HI 0               // 128 x 264 bf16 (row stride 528B)
#define OFF_A_LO 67584
#define OFF_B_HI 135168          // 256 x 40 bf16 (row stride 80B)
#define OFF_B_LO 155648
#define OFF_STAGE 135168         // aliases B region: 128 x 76 f32 (38912B <= 40960B)
#define OFF_BIAS 176128          // 256 f32
#define OFF_STAT 177152          // 128*20 f32
#define OFF_QW1  187904          // 64*20 f32
#define SMEM_BYTES 193024

#define A_STRIDE 528
#define B_STRIDE 80

// weight scratch (hi/lo split), written by prep kernel each launch
__device__ __nv_bfloat16 g_whi[4][65536];   // 0=rw1 1=rw2 2=cw1 3=cw2
__device__ __nv_bfloat16 g_wlo[4][65536];
__device__ __nv_bfloat16 g_w3hi[72 * 256];  // rw3 padded to 72 rows
__device__ __nv_bfloat16 g_w3lo[72 * 256];

// ---------------- helpers ----------------
__device__ __forceinline__ uint32_t smem_u32(const void* p) {
    uint32_t a;
    asm("{ .reg .u64 t; cvta.to.shared.u64 t, %1; cvt.u32.u64 %0, t; }"
        : "=r"(a) : "l"(p));
    return a;
}
__device__ __forceinline__ void ldsm4(uint32_t* r, uint32_t addr) {
    asm volatile("ldmatrix.sync.aligned.m8n8.x4.shared.b16 {%0,%1,%2,%3}, [%4];"
        : "=r"(r[0]), "=r"(r[1]), "=r"(r[2]), "=r"(r[3]) : "r"(addr));
}
__device__ __forceinline__ void mma16816(float* c, const uint32_t* a, const uint32_t* b) {
    asm volatile("mma.sync.aligned.m16n8k16.row.col.f32.bf16.bf16.f32 "
        "{%0,%1,%2,%3}, {%4,%5,%6,%7}, {%8,%9}, {%0,%1,%2,%3};"
        : "+f"(c[0]), "+f"(c[1]), "+f"(c[2]), "+f"(c[3])
        : "r"(a[0]), "r"(a[1]), "r"(a[2]), "r"(a[3]), "r"(b[0]), "r"(b[1]));
}
__device__ __forceinline__ void split2(float v, unsigned short& h, unsigned short& l) {
    __nv_bfloat16 bh = __float2bfloat16(v);
    float fh = __bfloat162float(bh);
    __nv_bfloat16 bl = __float2bfloat16(v - fh);
    h = *(unsigned short*)&bh;
    l = *(unsigned short*)&bl;
}
__device__ __forceinline__ float bf2f(unsigned short us) {
    __nv_bfloat16_raw r; r.x = us;
    return __bfloat162float(*(__nv_bfloat16*)&r);
}
__device__ __forceinline__ float sigmoidf_(float v) { return 1.0f / (1.0f + __expf(-v)); }

// ---------------- prep kernel ----------------
__global__ void prep_kernel(const float* rw1, const float* rw2,
                            const float* cw1, const float* cw2,
                            const float* rw3) {
    int i = blockIdx.x * 256 + threadIdx.x;
    if (i < 65536) {
        const float* srcs[4] = {rw1, rw2, cw1, cw2};
#pragma unroll
        for (int l = 0; l < 4; l++) {
            unsigned short h, lo;
            split2(srcs[l][i], h, lo);
            ((unsigned short*)g_whi[l])[i] = h;
            ((unsigned short*)g_wlo[l])[i] = lo;
        }
        if (i < 72 * 256) {
            int row = i >> 8;
            float v = (row < 68) ? rw3[i] : 0.0f;
            unsigned short h, lo;
            split2(v, h, lo);
            ((unsigned short*)g_w3hi)[i] = h;
            ((unsigned short*)g_w3lo)[i] = lo;
        }
    }
}

// ---------------- device subroutines ----------------
__device__ __forceinline__ void load_x_split(char* sm, const float* xg, int tid) {
    for (int idx = tid; idx < 8192; idx += THREADS) {
        int row = idx >> 6;
        int c4  = (idx & 63) << 2;
        float4 v = *(const float4*)(xg + row * 256 + c4);
        unsigned short h0,h1,h2,h3,l0,l1,l2,l3;
        split2(v.x,h0,l0); split2(v.y,h1,l1); split2(v.z,h2,l2); split2(v.w,h3,l3);
        uint2 uh, ul;
        uh.x = (uint32_t)h0 | ((uint32_t)h1 << 16);
        uh.y = (uint32_t)h2 | ((uint32_t)h3 << 16);
        ul.x = (uint32_t)l0 | ((uint32_t)l1 << 16);
        ul.y = (uint32_t)l2 | ((uint32_t)l3 << 16);
        *(uint2*)(sm + OFF_A_HI + row * A_STRIDE + c4 * 2) = uh;
        *(uint2*)(sm + OFF_A_LO + row * A_STRIDE + c4 * 2) = ul;
    }
}

// 128x256x256 layer: acc = A(smem hi/lo) @ W^T, W streamed in k-slices of 32
__device__ __forceinline__ void gemm256(char* sm, uint32_t smb,
    const __nv_bfloat16* __restrict__ whi, const __nv_bfloat16* __restrict__ wlo,
    float acc[2][8][4], int tid)
{
    const int lane = tid & 31, wid = tid >> 5;
    const int wm = wid >> 2, wn = wid & 3;
    const int a_row  = (lane & 7) + ((lane >> 3) & 1) * 8;
    const int a_koff = (lane >> 4) * 8;
    const int b_n    = (lane & 7) + ((lane >> 4) << 3);
    const int b_koff = ((lane >> 3) & 1) * 8;

    const uint32_t aHi = smb + OFF_A_HI + (uint32_t)((wm*32 + a_row) * A_STRIDE + a_koff * 2);
    const uint32_t aLo = aHi + (OFF_A_LO - OFF_A_HI);
    const uint32_t bHi = smb + OFF_B_HI + (uint32_t)((wn*64 + b_n) * B_STRIDE + b_koff * 2);
    const uint32_t bLo = bHi + (OFF_B_LO - OFF_B_HI);

    for (int ks = 0; ks < 8; ks++) {
        __syncthreads();
        for (int idx = tid; idx < 1024; idx += THREADS) {
            int row = idx >> 2, c8 = (idx & 3) << 3;
            *(uint4*)(sm + OFF_B_HI + row * B_STRIDE + c8 * 2) =
                *(const uint4*)(whi + row * 256 + ks * 32 + c8);
            *(uint4*)(sm + OFF_B_LO + row * B_STRIDE + c8 * 2) =
                *(const uint4*)(wlo + row * 256 + ks * 32 + c8);
        }
        __syncthreads();
#pragma unroll
        for (int h = 0; h < 2; h++) {
            uint32_t bh[8][2], bl[8][2];
#pragma unroll
            for (int p = 0; p < 4; p++) {
                uint32_t r[4];
                ldsm4(r, bHi + p * 16 * B_STRIDE + h * 32);
                bh[2*p][0]=r[0]; bh[2*p][1]=r[1]; bh[2*p+1][0]=r[2]; bh[2*p+1][1]=r[3];
                ldsm4(r, bLo + p * 16 * B_STRIDE + h * 32);
                bl[2*p][0]=r[0]; bl[2*p][1]=r[1]; bl[2*p+1][0]=r[2]; bl[2*p+1][1]=r[3];
            }
#pragma unroll
            for (int mt = 0; mt < 2; mt++) {
                uint32_t ah[4], al[4];
                uint32_t ao = (uint32_t)(mt * 16 * A_STRIDE + (ks * 32 + h * 16) * 2);
                ldsm4(ah, aHi + ao);
                ldsm4(al, aLo + ao);
#pragma unroll
                for (int nt = 0; nt < 8; nt++) {
                    mma16816(acc[mt][nt], ah, bh[nt]);
                    mma16816(acc[mt][nt], ah, bl[nt]);
                    mma16816(acc[mt][nt], al, bh[nt]);
                }
            }
        }
    }
    __syncthreads();
}

// bias + relu + hi/lo split -> A smem
__device__ __forceinline__ void epi256(char* sm, float acc[2][8][4], int tid) {
    const int lane = tid & 31, wid = tid >> 5, wm = wid >> 2, wn = wid & 3;
    const float* bias_s = (const float*)(sm + OFF_BIAS);
    const int r0 = wm * 32 + (lane >> 2);
    const int c0 = wn * 64 + (lane & 3) * 2;
#pragma unroll
    for (int mt = 0; mt < 2; mt++)
#pragma unroll
    for (int nt = 0; nt < 8; nt++) {
        int col = c0 + nt * 8;
        float b0 = bias_s[col], b1 = bias_s[col + 1];
        float v0 = fmaxf(acc[mt][nt][0] + b0, 0.f);
        float v1 = fmaxf(acc[mt][nt][1] + b1, 0.f);
        float v2 = fmaxf(acc[mt][nt][2] + b0, 0.f);
        float v3 = fmaxf(acc[mt][nt][3] + b1, 0.f);
        unsigned short h0,h1,h2,h3,l0,l1,l2,l3;
        split2(v0,h0,l0); split2(v1,h1,l1); split2(v2,h2,l2); split2(v3,h3,l3);
        uint32_t h01 = (uint32_t)h0 | ((uint32_t)h1 << 16);
        uint32_t l01 = (uint32_t)l0 | ((uint32_t)l1 << 16);
        uint32_t h23 = (uint32_t)h2 | ((uint32_t)h3 << 16);
        uint32_t l23 = (uint32_t)l2 | ((uint32_t)l3 << 16);
        int row = r0 + mt * 16;
        *(uint32_t*)(sm + OFF_A_HI + row * A_STRIDE + col * 2) = h01;
        *(uint32_t*)(sm + OFF_A_LO + row * A_STRIDE + col * 2) = l01;
        *(uint32_t*)(sm + OFF_A_HI + (row + 8) * A_STRIDE + col * 2) = h23;
        *(uint32_t*)(sm + OFF_A_LO + (row + 8) * A_STRIDE + col * 2) = l23;
    }
    __syncthreads();
}

// 128x72x256 layer (reg layer3). warp w: m-tile w>>1, n-half w&1 (5 tiles, last of nh=1 dummy)
__device__ __forceinline__ void gemm72(char* sm, uint32_t smb,
    const __nv_bfloat16* __restrict__ whi, const __nv_bfloat16* __restrict__ wlo,
    float acc[5][4], int tid)
{
    const int lane = tid & 31, wid = tid >> 5;
    const int mt8 = wid >> 1, nh = wid & 1;
    const int a_row  = (lane & 7) + ((lane >> 3) & 1) * 8;
    const int a_koff = (lane >> 4) * 8;
    const int b_n    = (lane & 7) + ((lane >> 4) << 3);
    const int b_koff = ((lane >> 3) & 1) * 8;

    const uint32_t aHi = smb + OFF_A_HI + (uint32_t)((mt8*16 + a_row) * A_STRIDE + a_koff * 2);
    const uint32_t aLo = aHi + (OFF_A_LO - OFF_A_HI);
    const uint32_t bHi = smb + OFF_B_HI + (uint32_t)((nh*40 + b_n) * B_STRIDE + b_koff * 2);
    const uint32_t bLo = bHi + (OFF_B_LO - OFF_B_HI);

    for (int ks = 0; ks < 8; ks++) {
        __syncthreads();
        for (int idx = tid; idx < 288; idx += THREADS) {
            int row = idx >> 2, c8 = (idx & 3) << 3;
            *(uint4*)(sm + OFF_B_HI + row * B_STRIDE + c8 * 2) =
                *(const uint4*)(whi + row * 256 + ks * 32 + c8);
            *(uint4*)(sm + OFF_B_LO + row * B_STRIDE + c8 * 2) =
                *(const uint4*)(wlo + row * 256 + ks * 32 + c8);
        }
        __syncthreads();
#pragma unroll
        for (int h = 0; h < 2; h++) {
            uint32_t bh[5][2], bl[5][2], r[4];
#pragma unroll
            for (int p = 0; p < 3; p++) {
                ldsm4(r, bHi + p * 16 * B_STRIDE + h * 32);
                bh[2*p][0] = r[0]; bh[2*p][1] = r[1];
                if (p < 2) { bh[2*p+1][0] = r[2]; bh[2*p+1][1] = r[3]; }
                ldsm4(r, bLo + p * 16 * B_STRIDE + h * 32);
                bl[2*p][0] = r[0]; bl[2*p][1] = r[1];
                if (p < 2) { bl[2*p+1][0] = r[2]; bl[2*p+1][1] = r[3]; }
            }
            uint32_t ah[4], al[4];
            uint32_t ao = (uint32_t)((ks * 32 + h * 16) * 2);
            ldsm4(ah, aHi + ao);
            ldsm4(al, aLo + ao);
#pragma unroll
            for (int nt = 0; nt < 5; nt++) {
                mma16816(acc[nt], ah, bh[nt]);
                mma16816(acc[nt], ah, bl[nt]);
                mma16816(acc[nt], al, bh[nt]);
            }
        }
    }
    __syncthreads();
}

// ---------------- main kernel ----------------
__global__ void __launch_bounds__(THREADS, 1) gfocal_mma_kernel(
    const float* __restrict__ x,
    const float* __restrict__ cb1, const float* __restrict__ cb2,
    const float* __restrict__ cw3, const float* __restrict__ cb3,
    const float* __restrict__ rb1, const float* __restrict__ rb2,
    const float* __restrict__ rb3,
    const float* __restrict__ qw1, const float* __restrict__ qb1,
    const float* __restrict__ qw2, const float* __restrict__ qb2,
    float* __restrict__ cls_out, float* __restrict__ box_out,
    float* __restrict__ reg_out)
{
    extern __shared__ char sm[];
    const uint32_t smb = smem_u32(sm);
    const int tid  = threadIdx.x;
    const int base = blockIdx.x * BM;

    float* bias_s = (float*)(sm + OFF_BIAS);
    float* stat_s = (float*)(sm + OFF_STAT);
    float* stage  = (float*)(sm + OFF_STAGE);
    float* qw1_s  = (float*)(sm + OFF_QW1);

    // constants into smem once
    for (int idx = tid; idx < 64 * 20; idx += THREADS) qw1_s[idx] = qw1[idx];

    float acc[2][8][4];

    // ================= REG branch =================
    if (tid < 256) bias_s[tid] = rb1[tid];
    load_x_split(sm, x + (size_t)base * 256, tid);
#pragma unroll
    for (int i = 0; i < 64; i++) ((float*)acc)[i] = 0.f;
    gemm256(sm, smb, g_whi[0], g_wlo[0], acc, tid);
    epi256(sm, acc, tid);

    if (tid < 256) bias_s[tid] = rb2[tid];
#pragma unroll
    for (int i = 0; i < 64; i++) ((float*)acc)[i] = 0.f;
    gemm256(sm, smb, g_whi[1], g_wlo[1], acc, tid);
    epi256(sm, acc, tid);

    if (tid < 72) bias_s[tid] = (tid < 68) ? rb3[tid] : 0.0f;
    {
        float acc3[5][4];
#pragma unroll
        for (int i = 0; i < 20; i++) ((float*)acc3)[i] = 0.f;
        gemm72(sm, smb, g_w3hi, g_w3lo, acc3, tid);
        // write logits(+bias) to stage
        const int lane = tid & 31, wid = tid >> 5;
        const int mt8 = wid >> 1, nh = wid & 1;
        const int r0 = mt8 * 16 + (lane >> 2);
        const int cb = (lane & 3) * 2;
#pragma unroll
        for (int nt = 0; nt < 5; nt++) {
            int g = nh * 5 + nt;
            if (g < 9) {
                int col = g * 8 + cb;
                float b0 = bias_s[col], b1 = bias_s[col + 1];
                stage[r0 * 76 + col]       = acc3[nt][0] + b0;
                stage[r0 * 76 + col + 1]   = acc3[nt][1] + b1;
                stage[(r0+8) * 76 + col]   = acc3[nt][2] + b0;
                stage[(r0+8) * 76 + col+1] = acc3[nt][3] + b1;
            }
        }
    }
    __syncthreads();

    // per-token epilogue: softmax / integral / top4 stats
    if (tid < 128) {
        const int m = tid;
#pragma unroll
        for (int g = 0; g < 4; g++) {
            float lg[17];
#pragma unroll
            for (int j = 0; j < 17; j++) lg[j] = stage[m * 76 + g * 17 + j];
            float mx = lg[0];
#pragma unroll
            for (int j = 1; j < 17; j++) mx = fmaxf(mx, lg[j]);
            float e[17], s = 0.f, si = 0.f;
#pragma unroll
            for (int j = 0; j < 17; j++) {
                e[j] = __expf(lg[j] - mx);
                s += e[j]; si += e[j] * (float)j;
            }
            box_out[(size_t)(base + m) * 4 + g] = si / (s * 16.0f);
            float inv = 1.0f / s, tsum = 0.f;
#pragma unroll
            for (int t4 = 0; t4 < 4; t4++) {
                float mv = -1.0f; int mi = 0;
#pragma unroll
                for (int j = 0; j < 17; j++)
                    if (e[j] > mv) { mv = e[j]; mi = j; }
                float tv = mv * inv;
                stat_s[m * 20 + g * 5 + t4] = tv;
                tsum += tv;
                e[mi] = -1.0f;
            }
            stat_s[m * 20 + g * 5 + 4] = tsum * 0.25f;
        }
    }
    // reg_pred store
    for (int idx = tid; idx < 128 * 68; idx += THREADS) {
        int row = idx / 68;
        int col = idx - row * 68;
        reg_out[(size_t)base * 68 + idx] = stage[row * 76 + col];
    }

    // ================= CLS branch =================
    if (tid < 256) bias_s[tid] = cb1[tid];    // epi-of-layer3 readers already synced
    load_x_split(sm, x + (size_t)base * 256, tid);
#pragma unroll
    for (int i = 0; i < 64; i++) ((float*)acc)[i] = 0.f;
    gemm256(sm, smb, g_whi[2], g_wlo[2], acc, tid);
    epi256(sm, acc, tid);

    if (tid < 256) bias_s[tid] = cb2[tid];
#pragma unroll
    for (int i = 0; i < 64; i++) ((float*)acc)[i] = 0.f;
    gemm256(sm, smb, g_whi[3], g_wlo[3], acc, tid);
    epi256(sm, acc, tid);

    // cls layer3 (scalar) + quality head + final fuse
    if (tid < 128) {
        const char* pa = sm + OFF_A_HI + tid * A_STRIDE;
        float sacc = cb3[0];
        for (int k0 = 0; k0 < 256; k0 += 8) {
            uint4 uh = *(const uint4*)(pa + k0 * 2);
            uint4 ul = *(const uint4*)(pa + (OFF_A_LO - OFF_A_HI) + k0 * 2);
            float4 w0 = *(const float4*)(cw3 + k0);
            float4 w1 = *(const float4*)(cw3 + k0 + 4);
            const uint32_t* ph = (const uint32_t*)&uh;
            const uint32_t* pl = (const uint32_t*)&ul;
            float wv[8] = {w0.x,w0.y,w0.z,w0.w,w1.x,w1.y,w1.z,w1.w};
#pragma unroll
            for (int e = 0; e < 8; e++) {
                unsigned short hs = (e & 1) ? (unsigned short)(ph[e>>1] >> 16) : (unsigned short)(ph[e>>1] & 0xffff);
                unsigned short ls = (e & 1) ? (unsigned short)(pl[e>>1] >> 16) : (unsigned short)(pl[e>>1] & 0xffff);
                sacc = fmaf(bf2f(hs) + bf2f(ls), wv[e], sacc);
            }
        }
        const float* st = stat_s + tid * 20;
        float q = qb2[0];
        for (int o = 0; o < 64; o++) {
            float hsum = qb1[o];
#pragma unroll
            for (int c = 0; c < 20; c++)
                hsum = fmaf(qw1_s[o * 20 + c], st[c], hsum);
            q = fmaf(fmaxf(hsum, 0.0f), qw2[o], q);
        }
        cls_out[base + tid] = sigmoidf_(sacc) * sigmoidf_(q);
    }
}

extern "C" void kernel_launch(void* const* d_in, const int* in_sizes, int n_in,
                              void* d_out, int out_size)
{
    const float* x   = (const float*)d_in[0];
    const float* cw1 = (const float*)d_in[1];
    const float* cb1 = (const float*)d_in[2];
    const float* cw2 = (const float*)d_in[3];
    const float* cb2 = (const float*)d_in[4];
    const float* cw3 = (const float*)d_in[5];
    const float* cb3 = (const float*)d_in[6];
    const float* rw1 = (const float*)d_in[7];
    const float* rb1 = (const float*)d_in[8];
    const float* rw2 = (const float*)d_in[9];
    const float* rb2 = (const float*)d_in[10];
    const float* rw3 = (const float*)d_in[11];
    const float* rb3 = (const float*)d_in[12];
    const float* qw1 = (const float*)d_in[13];
    const float* qb1 = (const float*)d_in[14];
    const float* qw2 = (const float*)d_in[15];
    const float* qb2 = (const float*)d_in[16];

    float* out = (float*)d_out;
    float* cls_out = out;
    float* box_out = out + NTOK;
    float* reg_out = out + NTOK + (size_t)NTOK * 4;

    prep_kernel<<<256, 256>>>(rw1, rw2, cw1, cw2, rw3);

    cudaFuncSetAttribute(gfocal_mma_kernel,
                         cudaFuncAttributeMaxDynamicSharedMemorySize, SMEM_BYTES);
    gfocal_mma_kernel<<<NBLK, THREADS, SMEM_BYTES>>>(
        x, cb1, cb2, cw3, cb3, rb1, rb2, rb3,
        qw1, qb1, qw2, qb2,
        cls_out, box_out, reg_out);
}

// round 4
// speedup vs baseline: 2.9740x; 1.3137x over previous
#include <cuda_runtime.h>
#include <cuda_bf16.h>
#include <stdint.h>

#define NTOK    294912
#define BM      128
#define NBLK    (NTOK / BM)      // 2304
#define THREADS 512

// ---- smem byte offsets ----
#define OFF_A_HI 0               // 128 x 264 bf16 (row stride 528B)
#define OFF_A_LO 67584
#define OFF_B    135168          // 3 stages x (hi 12288 + lo 12288)
#define BSTAGE   24576
#define BLO      12288
#define OFF_STAGE 135168         // aliases B region: 128 x 76 f32 (38912B)
#define OFF_BIAS 208896          // 256 f32
#define OFF_STAT 209920          // 128*20 f32
#define OFF_QW1  220160          // 64*20 f32
#define SMEM_BYTES 225280

#define A_STRIDE 528
#define B_STRIDE 48

// weight scratch (hi/lo split), written by prep kernel each launch
__device__ __nv_bfloat16 g_whi[4][65536];   // 0=rw1 1=rw2 2=cw1 3=cw2
__device__ __nv_bfloat16 g_wlo[4][65536];
__device__ __nv_bfloat16 g_w3hi[72 * 256];  // rw3 padded to 72 rows
__device__ __nv_bfloat16 g_w3lo[72 * 256];

// ---------------- helpers ----------------
__device__ __forceinline__ uint32_t smem_u32(const void* p) {
    uint32_t a;
    asm("{ .reg .u64 t; cvta.to.shared.u64 t, %1; cvt.u32.u64 %0, t; }"
        : "=r"(a) : "l"(p));
    return a;
}
__device__ __forceinline__ void ldsm4(uint32_t* r, uint32_t addr) {
    asm volatile("ldmatrix.sync.aligned.m8n8.x4.shared.b16 {%0,%1,%2,%3}, [%4];"
        : "=r"(r[0]), "=r"(r[1]), "=r"(r[2]), "=r"(r[3]) : "r"(addr));
}
__device__ __forceinline__ void mma16816(float* c, const uint32_t* a, const uint32_t* b) {
    asm volatile("mma.sync.aligned.m16n8k16.row.col.f32.bf16.bf16.f32 "
        "{%0,%1,%2,%3}, {%4,%5,%6,%7}, {%8,%9}, {%0,%1,%2,%3};"
        : "+f"(c[0]), "+f"(c[1]), "+f"(c[2]), "+f"(c[3])
        : "r"(a[0]), "r"(a[1]), "r"(a[2]), "r"(a[3]), "r"(b[0]), "r"(b[1]));
}
__device__ __forceinline__ void cp16(uint32_t dst, const void* src) {
    asm volatile("cp.async.cg.shared.global [%0], [%1], 16;" :: "r"(dst), "l"(src));
}
#define CP_COMMIT() asm volatile("cp.async.commit_group;" ::: "memory")
#define CP_WAIT1()  asm volatile("cp.async.wait_group 1;" ::: "memory")

__device__ __forceinline__ void split2(float v, unsigned short& h, unsigned short& l) {
    __nv_bfloat16 bh = __float2bfloat16(v);
    float fh = __bfloat162float(bh);
    __nv_bfloat16 bl = __float2bfloat16(v - fh);
    h = *(unsigned short*)&bh;
    l = *(unsigned short*)&bl;
}
__device__ __forceinline__ float bf2f(unsigned short us) {
    __nv_bfloat16_raw r; r.x = us;
    return __bfloat162float(*(__nv_bfloat16*)&r);
}
__device__ __forceinline__ float sigmoidf_(float v) { return 1.0f / (1.0f + __expf(-v)); }

// ---------------- prep kernel ----------------
__global__ void prep_kernel(const float* rw1, const float* rw2,
                            const float* cw1, const float* cw2,
                            const float* rw3) {
    int i = blockIdx.x * 256 + threadIdx.x;
    if (i < 65536) {
        const float* srcs[4] = {rw1, rw2, cw1, cw2};
#pragma unroll
        for (int l = 0; l < 4; l++) {
            unsigned short h, lo;
            split2(srcs[l][i], h, lo);
            ((unsigned short*)g_whi[l])[i] = h;
            ((unsigned short*)g_wlo[l])[i] = lo;
        }
        if (i < 72 * 256) {
            int row = i >> 8;
            float v = (row < 68) ? rw3[i] : 0.0f;
            unsigned short h, lo;
            split2(v, h, lo);
            ((unsigned short*)g_w3hi)[i] = h;
            ((unsigned short*)g_w3lo)[i] = lo;
        }
    }
}

// ---------------- device subroutines ----------------
__device__ __forceinline__ void load_x_split(char* sm, const float* xg, int tid) {
    for (int idx = tid; idx < 8192; idx += THREADS) {
        int row = idx >> 6;
        int c4  = (idx & 63) << 2;
        float4 v = *(const float4*)(xg + row * 256 + c4);
        unsigned short h0,h1,h2,h3,l0,l1,l2,l3;
        split2(v.x,h0,l0); split2(v.y,h1,l1); split2(v.z,h2,l2); split2(v.w,h3,l3);
        uint2 uh, ul;
        uh.x = (uint32_t)h0 | ((uint32_t)h1 << 16);
        uh.y = (uint32_t)h2 | ((uint32_t)h3 << 16);
        ul.x = (uint32_t)l0 | ((uint32_t)l1 << 16);
        ul.y = (uint32_t)l2 | ((uint32_t)l3 << 16);
        *(uint2*)(sm + OFF_A_HI + row * A_STRIDE + c4 * 2) = uh;
        *(uint2*)(sm + OFF_A_LO + row * A_STRIDE + c4 * 2) = ul;
    }
}

// 128x256x256 layer: acc = A(smem hi/lo) @ W^T. cp.async 3-stage k16 pipeline.
__device__ __forceinline__ void gemm256(char* sm, uint32_t smb,
    const __nv_bfloat16* __restrict__ whi, const __nv_bfloat16* __restrict__ wlo,
    float acc[2][8][4], int tid)
{
    const int lane = tid & 31, wid = tid >> 5;
    const int wm = wid >> 2, wn = wid & 3;
    const int a_row  = (lane & 7) + ((lane >> 3) & 1) * 8;
    const int a_koff = (lane >> 4) * 8;
    const int b_n    = (lane & 7) + ((lane >> 4) << 3);
    const int b_koff = ((lane >> 3) & 1) * 8;

    const uint32_t aHi = smb + OFF_A_HI + (uint32_t)((wm*32 + a_row) * A_STRIDE + a_koff * 2);
    const uint32_t aLo = aHi + (OFF_A_LO - OFF_A_HI);
    const uint32_t bOff = (uint32_t)((wn*64 + b_n) * B_STRIDE + b_koff * 2);

    const int row = tid >> 1, half = tid & 1;
    const uint32_t bdst = smb + OFF_B + (uint32_t)(row * B_STRIDE + half * 16);
    const __nv_bfloat16* sh = whi + row * 256 + half * 8;
    const __nv_bfloat16* sl = wlo + row * 256 + half * 8;

    // prologue: slices 0,1 into stages 0,1
    cp16(bdst, sh);                    cp16(bdst + BLO, sl);                    CP_COMMIT();
    cp16(bdst + BSTAGE, sh + 16);      cp16(bdst + BSTAGE + BLO, sl + 16);      CP_COMMIT();

    for (int ks = 0; ks < 16; ks++) {
        CP_WAIT1();
        __syncthreads();
        if (ks + 2 < 16) {
            uint32_t d2 = bdst + (uint32_t)(((ks + 2) % 3) * BSTAGE);
            cp16(d2, sh + (ks + 2) * 16);
            cp16(d2 + BLO, sl + (ks + 2) * 16);
        }
        CP_COMMIT();

        const uint32_t bb = smb + OFF_B + (uint32_t)((ks % 3) * BSTAGE) + bOff;
        uint32_t bh[8][2], bl[8][2];
#pragma unroll
        for (int p = 0; p < 4; p++) {
            uint32_t r[4];
            ldsm4(r, bb + p * (16 * B_STRIDE));
            bh[2*p][0]=r[0]; bh[2*p][1]=r[1]; bh[2*p+1][0]=r[2]; bh[2*p+1][1]=r[3];
            ldsm4(r, bb + BLO + p * (16 * B_STRIDE));
            bl[2*p][0]=r[0]; bl[2*p][1]=r[1]; bl[2*p+1][0]=r[2]; bl[2*p+1][1]=r[3];
        }
#pragma unroll
        for (int mt = 0; mt < 2; mt++) {
            uint32_t ah[4], al[4];
            uint32_t ao = (uint32_t)(mt * 16 * A_STRIDE + ks * 32);
            ldsm4(ah, aHi + ao);
            ldsm4(al, aLo + ao);
#pragma unroll
            for (int nt = 0; nt < 8; nt++) {
                mma16816(acc[mt][nt], ah, bh[nt]);
                mma16816(acc[mt][nt], ah, bl[nt]);
                mma16816(acc[mt][nt], al, bh[nt]);
            }
        }
    }
    __syncthreads();
}

// bias + relu + hi/lo split -> A smem
__device__ __forceinline__ void epi256(char* sm, float acc[2][8][4], int tid) {
    const int lane = tid & 31, wid = tid >> 5, wm = wid >> 2, wn = wid & 3;
    const float* bias_s = (const float*)(sm + OFF_BIAS);
    const int r0 = wm * 32 + (lane >> 2);
    const int c0 = wn * 64 + (lane & 3) * 2;
#pragma unroll
    for (int mt = 0; mt < 2; mt++)
#pragma unroll
    for (int nt = 0; nt < 8; nt++) {
        int col = c0 + nt * 8;
        float b0 = bias_s[col], b1 = bias_s[col + 1];
        float v0 = fmaxf(acc[mt][nt][0] + b0, 0.f);
        float v1 = fmaxf(acc[mt][nt][1] + b1, 0.f);
        float v2 = fmaxf(acc[mt][nt][2] + b0, 0.f);
        float v3 = fmaxf(acc[mt][nt][3] + b1, 0.f);
        unsigned short h0,h1,h2,h3,l0,l1,l2,l3;
        split2(v0,h0,l0); split2(v1,h1,l1); split2(v2,h2,l2); split2(v3,h3,l3);
        uint32_t h01 = (uint32_t)h0 | ((uint32_t)h1 << 16);
        uint32_t l01 = (uint32_t)l0 | ((uint32_t)l1 << 16);
        uint32_t h23 = (uint32_t)h2 | ((uint32_t)h3 << 16);
        uint32_t l23 = (uint32_t)l2 | ((uint32_t)l3 << 16);
        int rowi = r0 + mt * 16;
        *(uint32_t*)(sm + OFF_A_HI + rowi * A_STRIDE + col * 2) = h01;
        *(uint32_t*)(sm + OFF_A_LO + rowi * A_STRIDE + col * 2) = l01;
        *(uint32_t*)(sm + OFF_A_HI + (rowi + 8) * A_STRIDE + col * 2) = h23;
        *(uint32_t*)(sm + OFF_A_LO + (rowi + 8) * A_STRIDE + col * 2) = l23;
    }
    __syncthreads();
}

// 128x72x256 layer (reg layer3), same 3-stage pipeline.
__device__ __forceinline__ void gemm72(char* sm, uint32_t smb,
    const __nv_bfloat16* __restrict__ whi, const __nv_bfloat16* __restrict__ wlo,
    float acc[5][4], int tid)
{
    const int lane = tid & 31, wid = tid >> 5;
    const int mt8 = wid >> 1, nh = wid & 1;
    const int a_row  = (lane & 7) + ((lane >> 3) & 1) * 8;
    const int a_koff = (lane >> 4) * 8;
    const int b_n    = (lane & 7) + ((lane >> 4) << 3);
    const int b_koff = ((lane >> 3) & 1) * 8;

    const uint32_t aHi = smb + OFF_A_HI + (uint32_t)((mt8*16 + a_row) * A_STRIDE + a_koff * 2);
    const uint32_t aLo = aHi + (OFF_A_LO - OFF_A_HI);
    const uint32_t bOff = (uint32_t)((nh*40 + b_n) * B_STRIDE + b_koff * 2);

    const bool ld = tid < 144;
    const int row = tid >> 1, half = tid & 1;
    const uint32_t bdst = smb + OFF_B + (uint32_t)(row * B_STRIDE + half * 16);
    const __nv_bfloat16* sh = whi + row * 256 + half * 8;
    const __nv_bfloat16* sl = wlo + row * 256 + half * 8;

    if (ld) { cp16(bdst, sh); cp16(bdst + BLO, sl); }
    CP_COMMIT();
    if (ld) { cp16(bdst + BSTAGE, sh + 16); cp16(bdst + BSTAGE + BLO, sl + 16); }
    CP_COMMIT();

    for (int ks = 0; ks < 16; ks++) {
        CP_WAIT1();
        __syncthreads();
        if (ld && ks + 2 < 16) {
            uint32_t d2 = bdst + (uint32_t)(((ks + 2) % 3) * BSTAGE);
            cp16(d2, sh + (ks + 2) * 16);
            cp16(d2 + BLO, sl + (ks + 2) * 16);
        }
        CP_COMMIT();

        const uint32_t bb = smb + OFF_B + (uint32_t)((ks % 3) * BSTAGE) + bOff;
        uint32_t bh[5][2], bl[5][2], r[4];
#pragma unroll
        for (int p = 0; p < 3; p++) {
            ldsm4(r, bb + p * (16 * B_STRIDE));
            bh[2*p][0] = r[0]; bh[2*p][1] = r[1];
            if (p < 2) { bh[2*p+1][0] = r[2]; bh[2*p+1][1] = r[3]; }
            ldsm4(r, bb + BLO + p * (16 * B_STRIDE));
            bl[2*p][0] = r[0]; bl[2*p][1] = r[1];
            if (p < 2) { bl[2*p+1][0] = r[2]; bl[2*p+1][1] = r[3]; }
        }
        uint32_t ah[4], al[4];
        uint32_t ao = (uint32_t)(ks * 32);
        ldsm4(ah, aHi + ao);
        ldsm4(al, aLo + ao);
#pragma unroll
        for (int nt = 0; nt < 5; nt++) {
            mma16816(acc[nt], ah, bh[nt]);
            mma16816(acc[nt], ah, bl[nt]);
            mma16816(acc[nt], al, bh[nt]);
        }
    }
    __syncthreads();
}

// ---------------- main kernel ----------------
__global__ void __launch_bounds__(THREADS, 1) gfocal_mma_kernel(
    const float* __restrict__ x,
    const float* __restrict__ cb1, const float* __restrict__ cb2,
    const float* __restrict__ cw3, const float* __restrict__ cb3,
    const float* __restrict__ rb1, const float* __restrict__ rb2,
    const float* __restrict__ rb3,
    const float* __restrict__ qw1, const float* __restrict__ qb1,
    const float* __restrict__ qw2, const float* __restrict__ qb2,
    float* __restrict__ cls_out, float* __restrict__ box_out,
    float* __restrict__ reg_out)
{
    extern __shared__ char sm[];
    const uint32_t smb = smem_u32(sm);
    const int tid  = threadIdx.x;
    const int base = blockIdx.x * BM;

    float* bias_s = (float*)(sm + OFF_BIAS);
    float* stat_s = (float*)(sm + OFF_STAT);
    float* stage  = (float*)(sm + OFF_STAGE);
    float* qw1_s  = (float*)(sm + OFF_QW1);

    for (int idx = tid; idx < 64 * 20; idx += THREADS) qw1_s[idx] = qw1[idx];

    float acc[2][8][4];

    // ================= REG branch =================
    if (tid < 256) bias_s[tid] = rb1[tid];
    load_x_split(sm, x + (size_t)base * 256, tid);
#pragma unroll
    for (int i = 0; i < 64; i++) ((float*)acc)[i] = 0.f;
    gemm256(sm, smb, g_whi[0], g_wlo[0], acc, tid);
    epi256(sm, acc, tid);

    if (tid < 256) bias_s[tid] = rb2[tid];
#pragma unroll
    for (int i = 0; i < 64; i++) ((float*)acc)[i] = 0.f;
    gemm256(sm, smb, g_whi[1], g_wlo[1], acc, tid);
    epi256(sm, acc, tid);

    if (tid < 72) bias_s[tid] = (tid < 68) ? rb3[tid] : 0.0f;
    {
        float acc3[5][4];
#pragma unroll
        for (int i = 0; i < 20; i++) ((float*)acc3)[i] = 0.f;
        gemm72(sm, smb, g_w3hi, g_w3lo, acc3, tid);
        const int lane = tid & 31, wid = tid >> 5;
        const int mt8 = wid >> 1, nh = wid & 1;
        const int r0 = mt8 * 16 + (lane >> 2);
        const int cb = (lane & 3) * 2;
#pragma unroll
        for (int nt = 0; nt < 5; nt++) {
            int g = nh * 5 + nt;
            if (g < 9) {
                int col = g * 8 + cb;
                float b0 = bias_s[col], b1 = bias_s[col + 1];
                stage[r0 * 76 + col]       = acc3[nt][0] + b0;
                stage[r0 * 76 + col + 1]   = acc3[nt][1] + b1;
                stage[(r0+8) * 76 + col]   = acc3[nt][2] + b0;
                stage[(r0+8) * 76 + col+1] = acc3[nt][3] + b1;
            }
        }
    }
    __syncthreads();

    // per-token epilogue: softmax / integral / top4 stats
    if (tid < 128) {
        const int m = tid;
#pragma unroll
        for (int g = 0; g < 4; g++) {
            float lg[17];
#pragma unroll
            for (int j = 0; j < 17; j++) lg[j] = stage[m * 76 + g * 17 + j];
            float mx = lg[0];
#pragma unroll
            for (int j = 1; j < 17; j++) mx = fmaxf(mx, lg[j]);
            float e[17], s = 0.f, si = 0.f;
#pragma unroll
            for (int j = 0; j < 17; j++) {
                e[j] = __expf(lg[j] - mx);
                s += e[j]; si += e[j] * (float)j;
            }
            box_out[(size_t)(base + m) * 4 + g] = si / (s * 16.0f);
            float inv = 1.0f / s, tsum = 0.f;
#pragma unroll
            for (int t4 = 0; t4 < 4; t4++) {
                float mv = -1.0f; int mi = 0;
#pragma unroll
                for (int j = 0; j < 17; j++)
                    if (e[j] > mv) { mv = e[j]; mi = j; }
                float tv = mv * inv;
                stat_s[m * 20 + g * 5 + t4] = tv;
                tsum += tv;
                e[mi] = -1.0f;
            }
            stat_s[m * 20 + g * 5 + 4] = tsum * 0.25f;
        }
    }
    for (int idx = tid; idx < 128 * 68; idx += THREADS) {
        int row = idx / 68;
        int col = idx - row * 68;
        reg_out[(size_t)base * 68 + idx] = stage[row * 76 + col];
    }
    __syncthreads();   // stage (aliases B stages) fully read before CLS pipeline

    // ================= CLS branch =================
    if (tid < 256) bias_s[tid] = cb1[tid];
    load_x_split(sm, x + (size_t)base * 256, tid);
#pragma unroll
    for (int i = 0; i < 64; i++) ((float*)acc)[i] = 0.f;
    gemm256(sm, smb, g_whi[2], g_wlo[2], acc, tid);
    epi256(sm, acc, tid);

    if (tid < 256) bias_s[tid] = cb2[tid];
#pragma unroll
    for (int i = 0; i < 64; i++) ((float*)acc)[i] = 0.f;
    gemm256(sm, smb, g_whi[3], g_wlo[3], acc, tid);
    epi256(sm, acc, tid);

    // cls layer3 (scalar) + quality head + final fuse
    if (tid < 128) {
        const char* pa = sm + OFF_A_HI + tid * A_STRIDE;
        float sacc = cb3[0];
        for (int k0 = 0; k0 < 256; k0 += 8) {
            uint4 uh = *(const uint4*)(pa + k0 * 2);
            uint4 ul = *(const uint4*)(pa + (OFF_A_LO - OFF_A_HI) + k0 * 2);
            float4 w0 = *(const float4*)(cw3 + k0);
            float4 w1 = *(const float4*)(cw3 + k0 + 4);
            const uint32_t* ph = (const uint32_t*)&uh;
            const uint32_t* pl = (const uint32_t*)&ul;
            float wv[8] = {w0.x,w0.y,w0.z,w0.w,w1.x,w1.y,w1.z,w1.w};
#pragma unroll
            for (int e = 0; e < 8; e++) {
                unsigned short hs = (e & 1) ? (unsigned short)(ph[e>>1] >> 16) : (unsigned short)(ph[e>>1] & 0xffff);
                unsigned short ls = (e & 1) ? (unsigned short)(pl[e>>1] >> 16) : (unsigned short)(pl[e>>1] & 0xffff);
                sacc = fmaf(bf2f(hs) + bf2f(ls), wv[e], sacc);
            }
        }
        const float* st = stat_s + tid * 20;
        float q = qb2[0];
        for (int o = 0; o < 64; o++) {
            float hsum = qb1[o];
#pragma unroll
            for (int c = 0; c < 20; c++)
                hsum = fmaf(qw1_s[o * 20 + c], st[c], hsum);
            q = fmaf(fmaxf(hsum, 0.0f), qw2[o], q);
        }
        cls_out[base + tid] = sigmoidf_(sacc) * sigmoidf_(q);
    }
}

extern "C" void kernel_launch(void* const* d_in, const int* in_sizes, int n_in,
                              void* d_out, int out_size)
{
    const float* x   = (const float*)d_in[0];
    const float* cw1 = (const float*)d_in[1];
    const float* cb1 = (const float*)d_in[2];
    const float* cw2 = (const float*)d_in[3];
    const float* cb2 = (const float*)d_in[4];
    const float* cw3 = (const float*)d_in[5];
    const float* cb3 = (const float*)d_in[6];
    const float* rw1 = (const float*)d_in[7];
    const float* rb1 = (const float*)d_in[8];
    const float* rw2 = (const float*)d_in[9];
    const float* rb2 = (const float*)d_in[10];
    const float* rw3 = (const float*)d_in[11];
    const float* rb3 = (const float*)d_in[12];
    const float* qw1 = (const float*)d_in[13];
    const float* qb1 = (const float*)d_in[14];
    const float* qw2 = (const float*)d_in[15];
    const float* qb2 = (const float*)d_in[16];

    float* out = (float*)d_out;
    float* cls_out = out;
    float* box_out = out + NTOK;
    float* reg_out = out + NTOK + (size_t)NTOK * 4;

    prep_kernel<<<256, 256>>>(rw1, rw2, cw1, cw2, rw3);

    cudaFuncSetAttribute(gfocal_mma_kernel,
                         cudaFuncAttributeMaxDynamicSharedMemorySize, SMEM_BYTES);
    gfocal_mma_kernel<<<NBLK, THREADS, SMEM_BYTES>>>(
        x, cb1, cb2, cw3, cb3, rb1, rb2, rb3,
        qw1, qb1, qw2, qb2,
        cls_out, box_out, reg_out);
}

// round 5
// speedup vs baseline: 4.1189x; 1.3850x over previous
#include <cuda_runtime.h>
#include <cuda_fp16.h>
#include <stdint.h>

#define NTOK    294912
#define BM      64
#define NBLK    (NTOK / BM)      // 4608
#define THREADS 256

// ---- smem byte offsets ----
#define OFF_A_HI 0               // 64 x 264 fp16 (row stride 528B)
#define OFF_A_LO 33792
#define OFF_B    67584           // 3 stages x 12288 (Bh only)
#define BSTAGE   12288
#define OFF_STAGE OFF_B          // aliases B: 64 x 76 f32 (19456B)
#define OFF_QW1  (OFF_B + 20480) // aliases B tail: 64*20 f32 (5120B)
#define OFF_BIAS 104448          // 256 f32
#define OFF_STAT 105472          // 64*20 f32
#define SMEM_BYTES 110592

#define A_STRIDE 528
#define B_STRIDE 48

// fp16 weights, written by prep kernel each launch
__device__ __half g_wh[4][65536];    // 0=rw1 1=rw2 2=cw1 3=cw2
__device__ __half g_w3h[96 * 256];   // rw3 padded to 96 rows

// ---------------- helpers ----------------
__device__ __forceinline__ uint32_t smem_u32(const void* p) {
    uint32_t a;
    asm("{ .reg .u64 t; cvta.to.shared.u64 t, %1; cvt.u32.u64 %0, t; }"
        : "=r"(a) : "l"(p));
    return a;
}
__device__ __forceinline__ void ldsm4(uint32_t* r, uint32_t addr) {
    asm volatile("ldmatrix.sync.aligned.m8n8.x4.shared.b16 {%0,%1,%2,%3}, [%4];"
        : "=r"(r[0]), "=r"(r[1]), "=r"(r[2]), "=r"(r[3]) : "r"(addr));
}
__device__ __forceinline__ void mmaf16(float* c, const uint32_t* a, const uint32_t* b) {
    asm volatile("mma.sync.aligned.m16n8k16.row.col.f32.f16.f16.f32 "
        "{%0,%1,%2,%3}, {%4,%5,%6,%7}, {%8,%9}, {%0,%1,%2,%3};"
        : "+f"(c[0]), "+f"(c[1]), "+f"(c[2]), "+f"(c[3])
        : "r"(a[0]), "r"(a[1]), "r"(a[2]), "r"(a[3]), "r"(b[0]), "r"(b[1]));
}
__device__ __forceinline__ void cp16(uint32_t dst, const void* src) {
    asm volatile("cp.async.cg.shared.global [%0], [%1], 16;" :: "r"(dst), "l"(src));
}
#define CP_COMMIT() asm volatile("cp.async.commit_group;" ::: "memory")
#define CP_WAIT1()  asm volatile("cp.async.wait_group 1;" ::: "memory")

// exact fp16 hi/lo split of an fp32 value
__device__ __forceinline__ void split2h(float v, unsigned short& h, unsigned short& l) {
    __half hh = __float2half_rn(v);
    float fh = __half2float(hh);
    __half hl = __float2half_rn(v - fh);
    h = *(unsigned short*)&hh;
    l = *(unsigned short*)&hl;
}
__device__ __forceinline__ float h2f(unsigned short us) {
    __half_raw r; r.x = us;
    return __half2float(*(__half*)&r);
}
__device__ __forceinline__ float sigmoidf_(float v) { return 1.0f / (1.0f + __expf(-v)); }

// ---------------- prep kernel: weights -> fp16 ----------------
__global__ void prep_kernel(const float* rw1, const float* rw2,
                            const float* cw1, const float* cw2,
                            const float* rw3) {
    int i = blockIdx.x * 256 + threadIdx.x;
    if (i < 65536) {
        g_wh[0][i] = __float2half_rn(rw1[i]);
        g_wh[1][i] = __float2half_rn(rw2[i]);
        g_wh[2][i] = __float2half_rn(cw1[i]);
        g_wh[3][i] = __float2half_rn(cw2[i]);
        if (i < 96 * 256) {
            int row = i >> 8;
            g_w3h[i] = __float2half_rn((row < 68) ? rw3[i] : 0.0f);
        }
    }
}

// ---------------- device subroutines ----------------
__device__ __forceinline__ void load_x_split(char* sm, const float* xg, int tid) {
    for (int idx = tid; idx < 4096; idx += THREADS) {
        int row = idx >> 6;
        int c4  = (idx & 63) << 2;
        float4 v = *(const float4*)(xg + row * 256 + c4);
        unsigned short h0,h1,h2,h3,l0,l1,l2,l3;
        split2h(v.x,h0,l0); split2h(v.y,h1,l1); split2h(v.z,h2,l2); split2h(v.w,h3,l3);
        uint2 uh, ul;
        uh.x = (uint32_t)h0 | ((uint32_t)h1 << 16);
        uh.y = (uint32_t)h2 | ((uint32_t)h3 << 16);
        ul.x = (uint32_t)l0 | ((uint32_t)l1 << 16);
        ul.y = (uint32_t)l2 | ((uint32_t)l3 << 16);
        *(uint2*)(sm + OFF_A_HI + row * A_STRIDE + c4 * 2) = uh;
        *(uint2*)(sm + OFF_A_LO + row * A_STRIDE + c4 * 2) = ul;
    }
}

// 64x256x256 layer: acc = A(smem fp16 hi/lo) @ Wh^T. 3-stage cp.async k16 ring.
__device__ __forceinline__ void gemm256(char* sm, uint32_t smb,
    const __half* __restrict__ w, float acc[2][8][4], int tid)
{
    const int lane = tid & 31, wid = tid >> 5;
    const int wm = wid >> 2, wn = wid & 3;
    const int a_row  = (lane & 7) + ((lane >> 3) & 1) * 8;
    const int a_koff = (lane >> 4) * 8;
    const int b_n    = (lane & 7) + ((lane >> 4) << 3);
    const int b_koff = ((lane >> 3) & 1) * 8;

    const uint32_t aHi = smb + OFF_A_HI + (uint32_t)((wm*32 + a_row) * A_STRIDE + a_koff * 2);
    const uint32_t aLo = aHi + (OFF_A_LO - OFF_A_HI);
    const uint32_t bOff = (uint32_t)((wn*64 + b_n) * B_STRIDE + b_koff * 2);

    const uint32_t bdst = smb + OFF_B + (uint32_t)(tid * B_STRIDE);
    const __half* src = w + tid * 256;

    cp16(bdst, src);                cp16(bdst + 16, src + 8);                CP_COMMIT();
    cp16(bdst + BSTAGE, src + 16);  cp16(bdst + BSTAGE + 16, src + 24);      CP_COMMIT();

    for (int ks = 0; ks < 16; ks++) {
        CP_WAIT1();
        __syncthreads();
        if (ks + 2 < 16) {
            uint32_t d2 = bdst + (uint32_t)(((ks + 2) % 3) * BSTAGE);
            cp16(d2, src + (ks + 2) * 16);
            cp16(d2 + 16, src + (ks + 2) * 16 + 8);
        }
        CP_COMMIT();

        const uint32_t bb = smb + OFF_B + (uint32_t)((ks % 3) * BSTAGE) + bOff;
        uint32_t bh[8][2];
#pragma unroll
        for (int p = 0; p < 4; p++) {
            uint32_t r[4];
            ldsm4(r, bb + p * (16 * B_STRIDE));
            bh[2*p][0]=r[0]; bh[2*p][1]=r[1]; bh[2*p+1][0]=r[2]; bh[2*p+1][1]=r[3];
        }
#pragma unroll
        for (int mt = 0; mt < 2; mt++) {
            uint32_t ah[4], al[4];
            uint32_t ao = (uint32_t)(mt * 16 * A_STRIDE + ks * 32);
            ldsm4(ah, aHi + ao);
            ldsm4(al, aLo + ao);
#pragma unroll
            for (int nt = 0; nt < 8; nt++) mmaf16(acc[mt][nt], ah, bh[nt]);
#pragma unroll
            for (int nt = 0; nt < 8; nt++) mmaf16(acc[mt][nt], al, bh[nt]);
        }
    }
    __syncthreads();
}

// bias + relu + fp16 hi/lo split -> A smem
__device__ __forceinline__ void epi256(char* sm, float acc[2][8][4], int tid) {
    const int lane = tid & 31, wid = tid >> 5, wm = wid >> 2, wn = wid & 3;
    const float* bias_s = (const float*)(sm + OFF_BIAS);
    const int r0 = wm * 32 + (lane >> 2);
    const int c0 = wn * 64 + (lane & 3) * 2;
#pragma unroll
    for (int mt = 0; mt < 2; mt++)
#pragma unroll
    for (int nt = 0; nt < 8; nt++) {
        int col = c0 + nt * 8;
        float b0 = bias_s[col], b1 = bias_s[col + 1];
        float v0 = fmaxf(acc[mt][nt][0] + b0, 0.f);
        float v1 = fmaxf(acc[mt][nt][1] + b1, 0.f);
        float v2 = fmaxf(acc[mt][nt][2] + b0, 0.f);
        float v3 = fmaxf(acc[mt][nt][3] + b1, 0.f);
        unsigned short h0,h1,h2,h3,l0,l1,l2,l3;
        split2h(v0,h0,l0); split2h(v1,h1,l1); split2h(v2,h2,l2); split2h(v3,h3,l3);
        uint32_t h01 = (uint32_t)h0 | ((uint32_t)h1 << 16);
        uint32_t l01 = (uint32_t)l0 | ((uint32_t)l1 << 16);
        uint32_t h23 = (uint32_t)h2 | ((uint32_t)h3 << 16);
        uint32_t l23 = (uint32_t)l2 | ((uint32_t)l3 << 16);
        int rowi = r0 + mt * 16;
        *(uint32_t*)(sm + OFF_A_HI + rowi * A_STRIDE + col * 2) = h01;
        *(uint32_t*)(sm + OFF_A_LO + rowi * A_STRIDE + col * 2) = l01;
        *(uint32_t*)(sm + OFF_A_HI + (rowi + 8) * A_STRIDE + col * 2) = h23;
        *(uint32_t*)(sm + OFF_A_LO + (rowi + 8) * A_STRIDE + col * 2) = l23;
    }
    __syncthreads();
}

// 64x96x256 layer (reg layer3, N padded to 96). wn 0..2 active, n-tile 32.
__device__ __forceinline__ void gemm96(char* sm, uint32_t smb,
    const __half* __restrict__ w, float acc[2][4][4], int tid)
{
    const int lane = tid & 31, wid = tid >> 5;
    const int wm = wid >> 2, wn = wid & 3;
    const bool act = (wn < 3);
    const int a_row  = (lane & 7) + ((lane >> 3) & 1) * 8;
    const int a_koff = (lane >> 4) * 8;
    const int b_n    = (lane & 7) + ((lane >> 4) << 3);
    const int b_koff = ((lane >> 3) & 1) * 8;

    const uint32_t aHi = smb + OFF_A_HI + (uint32_t)((wm*32 + a_row) * A_STRIDE + a_koff * 2);
    const uint32_t aLo = aHi + (OFF_A_LO - OFF_A_HI);
    const uint32_t bOff = (uint32_t)((wn*32 + b_n) * B_STRIDE + b_koff * 2);

    const bool ld = tid < 192;
    const int row = tid >> 1, half = tid & 1;
    const uint32_t bdst = smb + OFF_B + (uint32_t)(row * B_STRIDE + half * 16);
    const __half* src = w + row * 256 + half * 8;

    if (ld) cp16(bdst, src);
    CP_COMMIT();
    if (ld) cp16(bdst + BSTAGE, src + 16);
    CP_COMMIT();

    for (int ks = 0; ks < 16; ks++) {
        CP_WAIT1();
        __syncthreads();
        if (ld && ks + 2 < 16) {
            uint32_t d2 = bdst + (uint32_t)(((ks + 2) % 3) * BSTAGE);
            cp16(d2, src + (ks + 2) * 16);
        }
        CP_COMMIT();

        if (act) {
            const uint32_t bb = smb + OFF_B + (uint32_t)((ks % 3) * BSTAGE) + bOff;
            uint32_t bh[4][2];
#pragma unroll
            for (int p = 0; p < 2; p++) {
                uint32_t r[4];
                ldsm4(r, bb + p * (16 * B_STRIDE));
                bh[2*p][0]=r[0]; bh[2*p][1]=r[1]; bh[2*p+1][0]=r[2]; bh[2*p+1][1]=r[3];
            }
#pragma unroll
            for (int mt = 0; mt < 2; mt++) {
                uint32_t ah[4], al[4];
                uint32_t ao = (uint32_t)(mt * 16 * A_STRIDE + ks * 32);
                ldsm4(ah, aHi + ao);
                ldsm4(al, aLo + ao);
#pragma unroll
                for (int nt = 0; nt < 4; nt++) mmaf16(acc[mt][nt], ah, bh[nt]);
#pragma unroll
                for (int nt = 0; nt < 4; nt++) mmaf16(acc[mt][nt], al, bh[nt]);
            }
        }
    }
    __syncthreads();
}

// ---------------- main kernel ----------------
__global__ void __launch_bounds__(THREADS, 2) gfocal_mma_kernel(
    const float* __restrict__ x,
    const float* __restrict__ cb1, const float* __restrict__ cb2,
    const float* __restrict__ cw3, const float* __restrict__ cb3,
    const float* __restrict__ rb1, const float* __restrict__ rb2,
    const float* __restrict__ rb3,
    const float* __restrict__ qw1, const float* __restrict__ qb1,
    const float* __restrict__ qw2, const float* __restrict__ qb2,
    float* __restrict__ cls_out, float* __restrict__ box_out,
    float* __restrict__ reg_out)
{
    extern __shared__ char sm[];
    const uint32_t smb = smem_u32(sm);
    const int tid  = threadIdx.x;
    const int base = blockIdx.x * BM;

    float* bias_s = (float*)(sm + OFF_BIAS);
    float* stat_s = (float*)(sm + OFF_STAT);
    float* stage  = (float*)(sm + OFF_STAGE);
    float* qw1_s  = (float*)(sm + OFF_QW1);

    float acc[2][8][4];

    // ================= REG branch =================
    if (tid < 256) bias_s[tid] = rb1[tid];
    load_x_split(sm, x + (size_t)base * 256, tid);
#pragma unroll
    for (int i = 0; i < 64; i++) ((float*)acc)[i] = 0.f;
    gemm256(sm, smb, g_wh[0], acc, tid);
    epi256(sm, acc, tid);

    if (tid < 256) bias_s[tid] = rb2[tid];
#pragma unroll
    for (int i = 0; i < 64; i++) ((float*)acc)[i] = 0.f;
    gemm256(sm, smb, g_wh[1], acc, tid);
    epi256(sm, acc, tid);

    if (tid < 68) bias_s[tid] = rb3[tid];
    __syncthreads();
    {
        float acc3[2][4][4];
#pragma unroll
        for (int i = 0; i < 32; i++) ((float*)acc3)[i] = 0.f;
        gemm96(sm, smb, g_w3h, acc3, tid);
        const int lane = tid & 31, wid = tid >> 5;
        const int wm = wid >> 2, wn = wid & 3;
        if (wn < 3) {
            const int r0 = wm * 32 + (lane >> 2);
            const int cb = (lane & 3) * 2;
#pragma unroll
            for (int mt = 0; mt < 2; mt++)
#pragma unroll
            for (int nt = 0; nt < 4; nt++) {
                int col = wn * 32 + nt * 8 + cb;
                if (col < 68) {
                    int r = r0 + mt * 16;
                    float b0 = bias_s[col], b1 = bias_s[col + 1];
                    stage[r * 76 + col]       = acc3[mt][nt][0] + b0;
                    stage[r * 76 + col + 1]   = acc3[mt][nt][1] + b1;
                    stage[(r+8) * 76 + col]   = acc3[mt][nt][2] + b0;
                    stage[(r+8) * 76 + col+1] = acc3[mt][nt][3] + b1;
                }
            }
        }
    }
    __syncthreads();

    // per-token epilogue: softmax / integral / top4 stats
    if (tid < 64) {
        const int m = tid;
#pragma unroll
        for (int g = 0; g < 4; g++) {
            float lg[17];
#pragma unroll
            for (int j = 0; j < 17; j++) lg[j] = stage[m * 76 + g * 17 + j];
            float mx = lg[0];
#pragma unroll
            for (int j = 1; j < 17; j++) mx = fmaxf(mx, lg[j]);
            float e[17], s = 0.f, si = 0.f;
#pragma unroll
            for (int j = 0; j < 17; j++) {
                e[j] = __expf(lg[j] - mx);
                s += e[j]; si += e[j] * (float)j;
            }
            box_out[(size_t)(base + m) * 4 + g] = si / (s * 16.0f);
            float inv = 1.0f / s, tsum = 0.f;
#pragma unroll
            for (int t4 = 0; t4 < 4; t4++) {
                float mv = -1.0f; int mi = 0;
#pragma unroll
                for (int j = 0; j < 17; j++)
                    if (e[j] > mv) { mv = e[j]; mi = j; }
                float tv = mv * inv;
                stat_s[m * 20 + g * 5 + t4] = tv;
                tsum += tv;
                e[mi] = -1.0f;
            }
            stat_s[m * 20 + g * 5 + 4] = tsum * 0.25f;
        }
    }
    for (int idx = tid; idx < 64 * 68; idx += THREADS) {
        int row = idx / 68;
        int col = idx - row * 68;
        reg_out[(size_t)base * 68 + idx] = stage[row * 76 + col];
    }
    __syncthreads();   // stage (aliases B stages) fully read before CLS pipeline

    // ================= CLS branch =================
    if (tid < 256) bias_s[tid] = cb1[tid];
    load_x_split(sm, x + (size_t)base * 256, tid);
#pragma unroll
    for (int i = 0; i < 64; i++) ((float*)acc)[i] = 0.f;
    gemm256(sm, smb, g_wh[2], acc, tid);
    epi256(sm, acc, tid);

    if (tid < 256) bias_s[tid] = cb2[tid];
#pragma unroll
    for (int i = 0; i < 64; i++) ((float*)acc)[i] = 0.f;
    gemm256(sm, smb, g_wh[3], acc, tid);
    epi256(sm, acc, tid);

    // cls layer3 (scalar fp32 over reconstructed h2)
    float sacc = 0.0f;
    if (tid < 64) {
        const char* pa = sm + OFF_A_HI + tid * A_STRIDE;
        sacc = cb3[0];
        for (int k0 = 0; k0 < 256; k0 += 8) {
            uint4 uh = *(const uint4*)(pa + k0 * 2);
            uint4 ul = *(const uint4*)(pa + (OFF_A_LO - OFF_A_HI) + k0 * 2);
            float4 w0 = *(const float4*)(cw3 + k0);
            float4 w1 = *(const float4*)(cw3 + k0 + 4);
            const uint32_t* ph = (const uint32_t*)&uh;
            const uint32_t* pl = (const uint32_t*)&ul;
            float wv[8] = {w0.x,w0.y,w0.z,w0.w,w1.x,w1.y,w1.z,w1.w};
#pragma unroll
            for (int e = 0; e < 8; e++) {
                unsigned short hs = (e & 1) ? (unsigned short)(ph[e>>1] >> 16) : (unsigned short)(ph[e>>1] & 0xffff);
                unsigned short ls = (e & 1) ? (unsigned short)(pl[e>>1] >> 16) : (unsigned short)(pl[e>>1] & 0xffff);
                sacc = fmaf(h2f(hs) + h2f(ls), wv[e], sacc);
            }
        }
    }
    // quality head: qw1 into smem (aliases B region, gemms all done)
    __syncthreads();
    for (int idx = tid; idx < 64 * 20; idx += THREADS) qw1_s[idx] = qw1[idx];
    __syncthreads();

    if (tid < 64) {
        const float* st = stat_s + tid * 20;
        float q = qb2[0];
        for (int o = 0; o < 64; o++) {
            float hsum = qb1[o];
#pragma unroll
            for (int c = 0; c < 20; c++)
                hsum = fmaf(qw1_s[o * 20 + c], st[c], hsum);
            q = fmaf(fmaxf(hsum, 0.0f), qw2[o], q);
        }
        cls_out[base + tid] = sigmoidf_(sacc) * sigmoidf_(q);
    }
}

extern "C" void kernel_launch(void* const* d_in, const int* in_sizes, int n_in,
                              void* d_out, int out_size)
{
    const float* x   = (const float*)d_in[0];
    const float* cw1 = (const float*)d_in[1];
    const float* cb1 = (const float*)d_in[2];
    const float* cw2 = (const float*)d_in[3];
    const float* cb2 = (const float*)d_in[4];
    const float* cw3 = (const float*)d_in[5];
    const float* cb3 = (const float*)d_in[6];
    const float* rw1 = (const float*)d_in[7];
    const float* rb1 = (const float*)d_in[8];
    const float* rw2 = (const float*)d_in[9];
    const float* rb2 = (const float*)d_in[10];
    const float* rw3 = (const float*)d_in[11];
    const float* rb3 = (const float*)d_in[12];
    const float* qw1 = (const float*)d_in[13];
    const float* qb1 = (const float*)d_in[14];
    const float* qw2 = (const float*)d_in[15];
    const float* qb2 = (const float*)d_in[16];

    float* out = (float*)d_out;
    float* cls_out = out;
    float* box_out = out + NTOK;
    float* reg_out = out + NTOK + (size_t)NTOK * 4;

    prep_kernel<<<256, 256>>>(rw1, rw2, cw1, cw2, rw3);

    cudaFuncSetAttribute(gfocal_mma_kernel,
                         cudaFuncAttributeMaxDynamicSharedMemorySize, SMEM_BYTES);
    gfocal_mma_kernel<<<NBLK, THREADS, SMEM_BYTES>>>(
        x, cb1, cb2, cw3, cb3, rb1, rb2, rb3,
        qw1, qb1, qw2, qb2,
        cls_out, box_out, reg_out);
}

// round 7
// speedup vs baseline: 4.5428x; 1.1029x over previous
#include <cuda_runtime.h>
#include <cuda_fp16.h>
#include <stdint.h>

#define NTOK    294912
#define BM      64
#define NBLK    (NTOK / BM)      // 4608
#define THREADS 256

// ---- smem byte offsets ----
#define OFF_A_HI 0               // 64 x 264 fp16 (row stride 528B)
#define OFF_A_LO 33792
#define OFF_B    67584           // 4 pairs x 3 stages x 3072B
#define PAIR_RING 9216
#define BSTG     3072
#define OFF_STAGE OFF_B          // aliases B: 64 x 76 f32 (19456B)
#define OFF_QW1  (OFF_B + 20480) // 64*20 f32
#define OFF_P1   (OFF_B + 26624) // 256 f32 partials (cls)
#define OFF_P2   (OFF_B + 27648) // 256 f32 partials (quality)
#define OFF_BIAS 104448          // 256 f32
#define OFF_STAT 105472          // 64*20 f32
#define SMEM_BYTES 110592

#define A_STRIDE 528
#define B_STRIDE 48

// fp16 weights, written by prep kernel each launch
__device__ __half g_wh[4][65536];    // 0=rw1 1=rw2 2=cw1 3=cw2
__device__ __half g_w3h[96 * 256];   // rw3 padded to 96 rows

// ---------------- helpers ----------------
__device__ __forceinline__ uint32_t smem_u32(const void* p) {
    uint32_t a;
    asm("{ .reg .u64 t; cvta.to.shared.u64 t, %1; cvt.u32.u64 %0, t; }"
        : "=r"(a) : "l"(p));
    return a;
}
__device__ __forceinline__ void ldsm4(uint32_t* r, uint32_t addr) {
    asm volatile("ldmatrix.sync.aligned.m8n8.x4.shared.b16 {%0,%1,%2,%3}, [%4];"
        : "=r"(r[0]), "=r"(r[1]), "=r"(r[2]), "=r"(r[3]) : "r"(addr));
}
__device__ __forceinline__ void mmaf16(float* c, const uint32_t* a, const uint32_t* b) {
    asm volatile("mma.sync.aligned.m16n8k16.row.col.f32.f16.f16.f32 "
        "{%0,%1,%2,%3}, {%4,%5,%6,%7}, {%8,%9}, {%0,%1,%2,%3};"
        : "+f"(c[0]), "+f"(c[1]), "+f"(c[2]), "+f"(c[3])
        : "r"(a[0]), "r"(a[1]), "r"(a[2]), "r"(a[3]), "r"(b[0]), "r"(b[1]));
}
__device__ __forceinline__ void cp16(uint32_t dst, const void* src) {
    asm volatile("cp.async.cg.shared.global [%0], [%1], 16;" :: "r"(dst), "l"(src));
}
#define CP_COMMIT() asm volatile("cp.async.commit_group;" ::: "memory")
#define CP_WAIT1()  asm volatile("cp.async.wait_group 1;" ::: "memory")
__device__ __forceinline__ void bar_pair(int id) {
    asm volatile("bar.sync %0, 64;" :: "r"(id) : "memory");
}

// exact fp16 hi/lo split of an fp32 value
__device__ __forceinline__ void split2h(float v, unsigned short& h, unsigned short& l) {
    __half hh = __float2half_rn(v);
    float fh = __half2float(hh);
    __half hl = __float2half_rn(v - fh);
    h = *(unsigned short*)&hh;
    l = *(unsigned short*)&hl;
}
__device__ __forceinline__ float h2f(unsigned short us) {
    __half_raw r; r.x = us;
    return __half2float(*(__half*)&r);
}
__device__ __forceinline__ float sigmoidf_(float v) { return 1.0f / (1.0f + __expf(-v)); }

// ---------------- prep kernel: weights -> fp16 ----------------
__global__ void prep_kernel(const float* rw1, const float* rw2,
                            const float* cw1, const float* cw2,
                            const float* rw3) {
    int i = blockIdx.x * 256 + threadIdx.x;
    if (i < 65536) {
        g_wh[0][i] = __float2half_rn(rw1[i]);
        g_wh[1][i] = __float2half_rn(rw2[i]);
        g_wh[2][i] = __float2half_rn(cw1[i]);
        g_wh[3][i] = __float2half_rn(cw2[i]);
        if (i < 96 * 256) {
            int row = i >> 8;
            g_w3h[i] = __float2half_rn((row < 68) ? rw3[i] : 0.0f);
        }
    }
}

// ---------------- device subroutines ----------------
__device__ __forceinline__ void load_x_split(char* sm, const float* xg, int tid) {
    for (int idx = tid; idx < 4096; idx += THREADS) {
        int row = idx >> 6;
        int c4  = (idx & 63) << 2;
        float4 v = *(const float4*)(xg + row * 256 + c4);
        unsigned short h0,h1,h2,h3,l0,l1,l2,l3;
        split2h(v.x,h0,l0); split2h(v.y,h1,l1); split2h(v.z,h2,l2); split2h(v.w,h3,l3);
        uint2 uh, ul;
        uh.x = (uint32_t)h0 | ((uint32_t)h1 << 16);
        uh.y = (uint32_t)h2 | ((uint32_t)h3 << 16);
        ul.x = (uint32_t)l0 | ((uint32_t)l1 << 16);
        ul.y = (uint32_t)l2 | ((uint32_t)l3 << 16);
        *(uint2*)(sm + OFF_A_HI + row * A_STRIDE + c4 * 2) = uh;
        *(uint2*)(sm + OFF_A_LO + row * A_STRIDE + c4 * 2) = ul;
    }
}

// 64x256x256 layer. Per-pair private 3-stage cp.async ring; pair-local barriers only.
__device__ __forceinline__ void gemm256(char* sm, uint32_t smb,
    const __half* __restrict__ w, float acc[2][8][4], int tid)
{
    const int lane = tid & 31, wid = tid >> 5;
    const int wm = wid >> 2, wn = wid & 3;
    const int a_row  = (lane & 7) + ((lane >> 3) & 1) * 8;
    const int a_koff = (lane >> 4) * 8;
    const int b_n    = (lane & 7) + ((lane >> 4) << 3);
    const int b_koff = ((lane >> 3) & 1) * 8;
    const int barid  = 1 + wn;

    const uint32_t aHi = smb + OFF_A_HI + (uint32_t)((wm*32 + a_row) * A_STRIDE + a_koff * 2);
    const uint32_t aLo = aHi + (OFF_A_LO - OFF_A_HI);
    const uint32_t pairbase = smb + OFF_B + (uint32_t)(wn * PAIR_RING);
    const uint32_t bOff = (uint32_t)(b_n * B_STRIDE + b_koff * 2);

    // this warp loads 32 of the pair's 64 rows (one row per lane, 32B per slice)
    const uint32_t bdst = pairbase + (uint32_t)((wm*32 + lane) * B_STRIDE);
    const __half* src = w + (wn*64 + wm*32 + lane) * 256;

    // prologue: slices 0,1 into stages 0,1
    cp16(bdst, src);               cp16(bdst + 16, src + 8);               CP_COMMIT();
    cp16(bdst + BSTG, src + 16);   cp16(bdst + BSTG + 16, src + 24);       CP_COMMIT();

    int st_rd = 0, st_wr = 2;
    for (int ks = 0; ks < 16; ks++) {
        CP_WAIT1();
        bar_pair(barid);
        if (ks + 2 < 16) {
            uint32_t d2 = bdst + (uint32_t)(st_wr * BSTG);
            const __half* s2 = src + (ks + 2) * 16;
            cp16(d2, s2);
            cp16(d2 + 16, s2 + 8);
        }
        CP_COMMIT();

        const uint32_t bb = pairbase + (uint32_t)(st_rd * BSTG) + bOff;
        st_rd = (st_rd == 2) ? 0 : st_rd + 1;
        st_wr = (st_wr == 2) ? 0 : st_wr + 1;

        uint32_t bh[8][2];
#pragma unroll
        for (int p = 0; p < 4; p++) {
            uint32_t r[4];
            ldsm4(r, bb + p * (16 * B_STRIDE));
            bh[2*p][0]=r[0]; bh[2*p][1]=r[1]; bh[2*p+1][0]=r[2]; bh[2*p+1][1]=r[3];
        }
#pragma unroll
        for (int mt = 0; mt < 2; mt++) {
            uint32_t ah[4], al[4];
            uint32_t ao = (uint32_t)(mt * 16 * A_STRIDE + ks * 32);
            ldsm4(ah, aHi + ao);
            ldsm4(al, aLo + ao);
#pragma unroll
            for (int nt = 0; nt < 8; nt++) mmaf16(acc[mt][nt], ah, bh[nt]);
#pragma unroll
            for (int nt = 0; nt < 8; nt++) mmaf16(acc[mt][nt], al, bh[nt]);
        }
    }
    __syncthreads();   // before epilogue rewrites A
}

// bias + relu + fp16 hi/lo split -> A smem
__device__ __forceinline__ void epi256(char* sm, float acc[2][8][4], int tid) {
    const int lane = tid & 31, wid = tid >> 5, wm = wid >> 2, wn = wid & 3;
    const float* bias_s = (const float*)(sm + OFF_BIAS);
    const int r0 = wm * 32 + (lane >> 2);
    const int c0 = wn * 64 + (lane & 3) * 2;
#pragma unroll
    for (int mt = 0; mt < 2; mt++)
#pragma unroll
    for (int nt = 0; nt < 8; nt++) {
        int col = c0 + nt * 8;
        float b0 = bias_s[col], b1 = bias_s[col + 1];
        float v0 = fmaxf(acc[mt][nt][0] + b0, 0.f);
        float v1 = fmaxf(acc[mt][nt][1] + b1, 0.f);
        float v2 = fmaxf(acc[mt][nt][2] + b0, 0.f);
        float v3 = fmaxf(acc[mt][nt][3] + b1, 0.f);
        unsigned short h0,h1,h2,h3,l0,l1,l2,l3;
        split2h(v0,h0,l0); split2h(v1,h1,l1); split2h(v2,h2,l2); split2h(v3,h3,l3);
        uint32_t h01 = (uint32_t)h0 | ((uint32_t)h1 << 16);
        uint32_t l01 = (uint32_t)l0 | ((uint32_t)l1 << 16);
        uint32_t h23 = (uint32_t)h2 | ((uint32_t)h3 << 16);
        uint32_t l23 = (uint32_t)l2 | ((uint32_t)l3 << 16);
        int rowi = r0 + mt * 16;
        *(uint32_t*)(sm + OFF_A_HI + rowi * A_STRIDE + col * 2) = h01;
        *(uint32_t*)(sm + OFF_A_LO + rowi * A_STRIDE + col * 2) = l01;
        *(uint32_t*)(sm + OFF_A_HI + (rowi + 8) * A_STRIDE + col * 2) = h23;
        *(uint32_t*)(sm + OFF_A_LO + (rowi + 8) * A_STRIDE + col * 2) = l23;
    }
    __syncthreads();
}

// 64x96x256 layer (reg layer3, N padded to 96). Pairs wn<3 own 32 rows each.
__device__ __forceinline__ void gemm96(char* sm, uint32_t smb,
    const __half* __restrict__ w, float acc[2][4][4], int tid)
{
    const int lane = tid & 31, wid = tid >> 5;
    const int wm = wid >> 2, wn = wid & 3;
    if (wn >= 3) { __syncthreads(); return; }
    const int a_row  = (lane & 7) + ((lane >> 3) & 1) * 8;
    const int a_koff = (lane >> 4) * 8;
    const int b_n    = (lane & 7) + ((lane >> 4) << 3);
    const int b_koff = ((lane >> 3) & 1) * 8;
    const int barid  = 1 + wn;

    const uint32_t aHi = smb + OFF_A_HI + (uint32_t)((wm*32 + a_row) * A_STRIDE + a_koff * 2);
    const uint32_t aLo = aHi + (OFF_A_LO - OFF_A_HI);
    const uint32_t pairbase = smb + OFF_B + (uint32_t)(wn * PAIR_RING);
    const uint32_t bOff = (uint32_t)(b_n * B_STRIDE + b_koff * 2);

    // pair owns 32 rows; 64 threads -> half-row (16B) each per slice
    const int idx = wm * 32 + lane;          // 0..63
    const int row = idx >> 1, half = idx & 1;
    const uint32_t bdst = pairbase + (uint32_t)(row * B_STRIDE + half * 16);
    const __half* src = w + (wn*32 + row) * 256 + half * 8;

    cp16(bdst, src);              CP_COMMIT();
    cp16(bdst + BSTG, src + 16);  CP_COMMIT();

    int st_rd = 0, st_wr = 2;
    for (int ks = 0; ks < 16; ks++) {
        CP_WAIT1();
        bar_pair(barid);
        if (ks + 2 < 16)
            cp16(bdst + (uint32_t)(st_wr * BSTG), src + (ks + 2) * 16);
        CP_COMMIT();

        const uint32_t bb = pairbase + (uint32_t)(st_rd * BSTG) + bOff;
        st_rd = (st_rd == 2) ? 0 : st_rd + 1;
        st_wr = (st_wr == 2) ? 0 : st_wr + 1;

        uint32_t bh[4][2];
#pragma unroll
        for (int p = 0; p < 2; p++) {
            uint32_t r[4];
            ldsm4(r, bb + p * (16 * B_STRIDE));
            bh[2*p][0]=r[0]; bh[2*p][1]=r[1]; bh[2*p+1][0]=r[2]; bh[2*p+1][1]=r[3];
        }
#pragma unroll
        for (int mt = 0; mt < 2; mt++) {
            uint32_t ah[4], al[4];
            uint32_t ao = (uint32_t)(mt * 16 * A_STRIDE + ks * 32);
            ldsm4(ah, aHi + ao);
            ldsm4(al, aLo + ao);
#pragma unroll
            for (int nt = 0; nt < 4; nt++) mmaf16(acc[mt][nt], ah, bh[nt]);
#pragma unroll
            for (int nt = 0; nt < 4; nt++) mmaf16(acc[mt][nt], al, bh[nt]);
        }
    }
    __syncthreads();
}

// ---------------- main kernel ----------------
__global__ void __launch_bounds__(THREADS, 2) gfocal_mma_kernel(
    const float* __restrict__ x,
    const float* __restrict__ cb1, const float* __restrict__ cb2,
    const float* __restrict__ cw3, const float* __restrict__ cb3,
    const float* __restrict__ rb1, const float* __restrict__ rb2,
    const float* __restrict__ rb3,
    const float* __restrict__ qw1, const float* __restrict__ qb1,
    const float* __restrict__ qw2, const float* __restrict__ qb2,
    float* __restrict__ cls_out, float* __restrict__ box_out,
    float* __restrict__ reg_out)
{
    extern __shared__ char sm[];
    const uint32_t smb = smem_u32(sm);
    const int tid  = threadIdx.x;
    const int base = blockIdx.x * BM;

    float* bias_s = (float*)(sm + OFF_BIAS);
    float* stat_s = (float*)(sm + OFF_STAT);
    float* stage  = (float*)(sm + OFF_STAGE);
    float* qw1_s  = (float*)(sm + OFF_QW1);
    float* p1_s   = (float*)(sm + OFF_P1);
    float* p2_s   = (float*)(sm + OFF_P2);

    float acc[2][8][4];

    // ================= REG branch =================
    if (tid < 256) bias_s[tid] = rb1[tid];
    load_x_split(sm, x + (size_t)base * 256, tid);
    __syncthreads();
#pragma unroll
    for (int i = 0; i < 64; i++) ((float*)acc)[i] = 0.f;
    gemm256(sm, smb, g_wh[0], acc, tid);
    epi256(sm, acc, tid);

    if (tid < 256) bias_s[tid] = rb2[tid];
#pragma unroll
    for (int i = 0; i < 64; i++) ((float*)acc)[i] = 0.f;
    gemm256(sm, smb, g_wh[1], acc, tid);
    epi256(sm, acc, tid);

    if (tid < 68) bias_s[tid] = rb3[tid];
    __syncthreads();
    {
        float acc3[2][4][4];
#pragma unroll
        for (int i = 0; i < 32; i++) ((float*)acc3)[i] = 0.f;
        gemm96(sm, smb, g_w3h, acc3, tid);
        const int lane = tid & 31, wid = tid >> 5;
        const int wm = wid >> 2, wn = wid & 3;
        if (wn < 3) {
            const int r0 = wm * 32 + (lane >> 2);
            const int cb = (lane & 3) * 2;
#pragma unroll
            for (int mt = 0; mt < 2; mt++)
#pragma unroll
            for (int nt = 0; nt < 4; nt++) {
                int col = wn * 32 + nt * 8 + cb;
                if (col < 68) {
                    int r = r0 + mt * 16;
                    float b0 = bias_s[col], b1 = bias_s[col + 1];
                    stage[r * 76 + col]       = acc3[mt][nt][0] + b0;
                    stage[r * 76 + col + 1]   = acc3[mt][nt][1] + b1;
                    stage[(r+8) * 76 + col]   = acc3[mt][nt][2] + b0;
                    stage[(r+8) * 76 + col+1] = acc3[mt][nt][3] + b1;
                }
            }
        }
    }
    __syncthreads();

    // per-(token,side) epilogue: softmax / integral / top4 stats — 256-way
    {
        const int m = tid >> 2, g = tid & 3;
        float lg[17];
#pragma unroll
        for (int j = 0; j < 17; j++) lg[j] = stage[m * 76 + g * 17 + j];
        float mx = lg[0];
#pragma unroll
        for (int j = 1; j < 17; j++) mx = fmaxf(mx, lg[j]);
        float e[17], s = 0.f, si = 0.f;
#pragma unroll
        for (int j = 0; j < 17; j++) {
            e[j] = __expf(lg[j] - mx);
            s += e[j]; si += e[j] * (float)j;
        }
        box_out[(size_t)(base + m) * 4 + g] = si / (s * 16.0f);
        float inv = 1.0f / s, tsum = 0.f;
#pragma unroll
        for (int t4 = 0; t4 < 4; t4++) {
            float mv = -1.0f; int mi = 0;
#pragma unroll
            for (int j = 0; j < 17; j++)
                if (e[j] > mv) { mv = e[j]; mi = j; }
            float tv = mv * inv;
            stat_s[m * 20 + g * 5 + t4] = tv;
            tsum += tv;
            e[mi] = -1.0f;
        }
        stat_s[m * 20 + g * 5 + 4] = tsum * 0.25f;
    }
    for (int idx = tid; idx < 64 * 68; idx += THREADS) {
        int row = idx / 68;
        int col = idx - row * 68;
        reg_out[(size_t)base * 68 + idx] = stage[row * 76 + col];
    }
    __syncthreads();   // stage (aliases B region) fully read before CLS pipeline

    // ================= CLS branch =================
    if (tid < 256) bias_s[tid] = cb1[tid];
    load_x_split(sm, x + (size_t)base * 256, tid);
    __syncthreads();
#pragma unroll
    for (int i = 0; i < 64; i++) ((float*)acc)[i] = 0.f;
    gemm256(sm, smb, g_wh[2], acc, tid);
    epi256(sm, acc, tid);

    if (tid < 256) bias_s[tid] = cb2[tid];
#pragma unroll
    for (int i = 0; i < 64; i++) ((float*)acc)[i] = 0.f;
    gemm256(sm, smb, g_wh[3], acc, tid);
    epi256(sm, acc, tid);

    // cls layer3 partials (4-way K split) + qw1 smem load
    {
        const int m = tid & 63, qtr = tid >> 6;
        const char* pa = sm + OFF_A_HI + m * A_STRIDE;
        float p = 0.0f;
        const int k_begin = qtr * 64;
        for (int k0 = k_begin; k0 < k_begin + 64; k0 += 8) {
            uint4 uh = *(const uint4*)(pa + k0 * 2);
            uint4 ul = *(const uint4*)(pa + (OFF_A_LO - OFF_A_HI) + k0 * 2);
            float4 w0 = *(const float4*)(cw3 + k0);
            float4 w1 = *(const float4*)(cw3 + k0 + 4);
            const uint32_t* ph = (const uint32_t*)&uh;
            const uint32_t* pl = (const uint32_t*)&ul;
            float wv[8] = {w0.x,w0.y,w0.z,w0.w,w1.x,w1.y,w1.z,w1.w};
#pragma unroll
            for (int e = 0; e < 8; e++) {
                unsigned short hs = (e & 1) ? (unsigned short)(ph[e>>1] >> 16) : (unsigned short)(ph[e>>1] & 0xffff);
                unsigned short ls = (e & 1) ? (unsigned short)(pl[e>>1] >> 16) : (unsigned short)(pl[e>>1] & 0xffff);
                p = fmaf(h2f(hs) + h2f(ls), wv[e], p);
            }
        }
        p1_s[tid] = p;
    }
    for (int idx = tid; idx < 64 * 20; idx += THREADS) qw1_s[idx] = qw1[idx];
    __syncthreads();

    // quality head partials (4-way O split)
    {
        const int m = tid & 63, ch = tid >> 6;
        const float* st = stat_s + m * 20;
        float qp = 0.0f;
        for (int o = ch * 16; o < ch * 16 + 16; o++) {
            float hsum = qb1[o];
#pragma unroll
            for (int c = 0; c < 20; c++)
                hsum = fmaf(qw1_s[o * 20 + c], st[c], hsum);
            qp = fmaf(fmaxf(hsum, 0.0f), qw2[o], qp);
        }
        p2_s[tid] = qp;
    }
    __syncthreads();

    if (tid < 64) {
        float sacc = cb3[0] + p1_s[tid] + p1_s[tid+64] + p1_s[tid+128] + p1_s[tid+192];
        float q    = qb2[0] + p2_s[tid] + p2_s[tid+64] + p2_s[tid+128] + p2_s[tid+192];
        cls_out[base + tid] = sigmoidf_(sacc) * sigmoidf_(q);
    }
}

extern "C" void kernel_launch(void* const* d_in, const int* in_sizes, int n_in,
                              void* d_out, int out_size)
{
    const float* x   = (const float*)d_in[0];
    const float* cw1 = (const float*)d_in[1];
    const float* cb1 = (const float*)d_in[2];
    const float* cw2 = (const float*)d_in[3];
    const float* cb2 = (const float*)d_in[4];
    const float* cw3 = (const float*)d_in[5];
    const float* cb3 = (const float*)d_in[6];
    const float* rw1 = (const float*)d_in[7];
    const float* rb1 = (const float*)d_in[8];
    const float* rw2 = (const float*)d_in[9];
    const float* rb2 = (const float*)d_in[10];
    const float* rw3 = (const float*)d_in[11];
    const float* rb3 = (const float*)d_in[12];
    const float* qw1 = (const float*)d_in[13];
    const float* qb1 = (const float*)d_in[14];
    const float* qw2 = (const float*)d_in[15];
    const float* qb2 = (const float*)d_in[16];

    float* out = (float*)d_out;
    float* cls_out = out;
    float* box_out = out + NTOK;
    float* reg_out = out + NTOK + (size_t)NTOK * 4;

    prep_kernel<<<256, 256>>>(rw1, rw2, cw1, cw2, rw3);

    cudaFuncSetAttribute(gfocal_mma_kernel,
                         cudaFuncAttributeMaxDynamicSharedMemorySize, SMEM_BYTES);
    gfocal_mma_kernel<<<NBLK, THREADS, SMEM_BYTES>>>(
        x, cb1, cb2, cw3, cb3, rb1, rb2, rb3,
        qw1, qb1, qw2, qb2,
        cls_out, box_out, reg_out);
}